// round 11
// baseline (speedup 1.0000x reference)
#include <cuda_runtime.h>
#include <cuda_fp16.h>
#include <cstdint>
#include <math.h>

// ---------------- problem constants ----------------
constexpr int kB    = 8;
constexpr int kGrid = 128;
constexpr int kNtok = kGrid * kGrid;
constexpr int kC    = 256;
constexpr int kM    = kB * kNtok;     // 131072 tokens
constexpr int kHid  = 1024;
constexpr int kNWin = kB * 256;       // 2048 windows
constexpr int kPersistGrid = 296;     // 2 x 148 SMs (<= resident on 148/152-SM parts)

// ---------------- scratch ----------------
__device__ __half g_big[(size_t)kM * kHid];
__device__ __half g_a  [(size_t)kM * kC];
__device__ __half g_b  [(size_t)kM * kC];
__device__ float  g_c  [(size_t)kM * kC];
__device__ __half g_w  [786432];

__device__ __forceinline__ int win_to_nat(int m) {
    int win = m >> 6;
    int t   = m & 63;
    int b   = win >> 8;
    int wi  = win & 255;
    int row = ((wi >> 4) << 3) + (t >> 3);
    int col = ((wi & 15) << 3) + (t & 7);
    return b * kNtok + row * kGrid + col;
}

__device__ __forceinline__ float gelu_exact(float x) {
    return 0.5f * x * (1.0f + erff(x * 0.70710678118654752f));
}

__device__ __forceinline__ void cpa16(__half* s, const __half* g) {
    uint32_t sa = (uint32_t)__cvta_generic_to_shared(s);
    asm volatile("cp.async.cg.shared.global [%0], [%1], 16;" :: "r"(sa), "l"(g));
}

__device__ __forceinline__ void mma16816(float* c, uint32_t a0, uint32_t a1,
                                         uint32_t a2, uint32_t a3,
                                         uint32_t b0, uint32_t b1) {
    asm volatile(
        "mma.sync.aligned.m16n8k16.row.col.f32.f16.f16.f32 "
        "{%0,%1,%2,%3}, {%4,%5,%6,%7}, {%8,%9}, {%0,%1,%2,%3};"
        : "+f"(c[0]), "+f"(c[1]), "+f"(c[2]), "+f"(c[3])
        : "r"(a0), "r"(a1), "r"(a2), "r"(a3), "r"(b0), "r"(b1));
}

__device__ __forceinline__ void ldsm4(uint32_t* r, uint32_t addr) {
    asm volatile("ldmatrix.sync.aligned.m8n8.x4.shared.b16 {%0,%1,%2,%3}, [%4];"
        : "=r"(r[0]), "=r"(r[1]), "=r"(r[2]), "=r"(r[3]) : "r"(addr));
}
__device__ __forceinline__ void ldsm4t(uint32_t* r, uint32_t addr) {
    asm volatile("ldmatrix.sync.aligned.m8n8.x4.trans.shared.b16 {%0,%1,%2,%3}, [%4];"
        : "=r"(r[0]), "=r"(r[1]), "=r"(r[2]), "=r"(r[3]) : "r"(addr));
}

__device__ __forceinline__ uint32_t packh2(float x, float y) {
    __half2 h = __floats2half2_rn(x, y);
    return *(uint32_t*)&h;
}

// ---------------- fp16 weight conversion (single launch) ----------------
__global__ __launch_bounds__(256) void cvtw_all(
    const float* __restrict__ in_w, const float* __restrict__ out_w,
    const float* __restrict__ w1, const float* __restrict__ w2,
    __half* __restrict__ o)
{
    int i = blockIdx.x * 256 + threadIdx.x;
    const float* src;
    int off;
    if (i < 196608)      { src = in_w;  off = i; }
    else if (i < 262144) { src = out_w; off = i - 196608; }
    else if (i < 524288) { src = w1;    off = i - 262144; }
    else                 { src = w2;    off = i - 524288; }
    o[i] = __float2half(src[off]);
}

// ---------------- LayerNorm (LN1): natural -> windowed, half out ----------
__global__ __launch_bounds__(256) void ln_kernel(
    const float* __restrict__ in, const float* __restrict__ g,
    const float* __restrict__ b, __half* __restrict__ out)
{
    int row  = blockIdx.x * 8 + (threadIdx.x >> 5);
    int lane = threadIdx.x & 31;
    int src  = win_to_nat(row);

    const float4* p = (const float4*)(in + (size_t)src * kC);
    float4 v0 = p[lane];
    float4 v1 = p[lane + 32];

    float s  = v0.x + v0.y + v0.z + v0.w + v1.x + v1.y + v1.z + v1.w;
    float s2 = v0.x*v0.x + v0.y*v0.y + v0.z*v0.z + v0.w*v0.w
             + v1.x*v1.x + v1.y*v1.y + v1.z*v1.z + v1.w*v1.w;
    #pragma unroll
    for (int off = 16; off > 0; off >>= 1) {
        s  += __shfl_xor_sync(0xffffffffu, s,  off);
        s2 += __shfl_xor_sync(0xffffffffu, s2, off);
    }
    float mean = s * (1.0f / kC);
    float var  = s2 * (1.0f / kC) - mean * mean;
    float inv  = rsqrtf(var + 1e-5f);

    const float4* gp = (const float4*)g;
    const float4* bp = (const float4*)b;
    float4 g0 = gp[lane], g1 = gp[lane + 32];
    float4 b0 = bp[lane], b1 = bp[lane + 32];

    __half2 h0 = __floats2half2_rn((v0.x - mean) * inv * g0.x + b0.x,
                                   (v0.y - mean) * inv * g0.y + b0.y);
    __half2 h1 = __floats2half2_rn((v0.z - mean) * inv * g0.z + b0.z,
                                   (v0.w - mean) * inv * g0.w + b0.w);
    __half2 h2 = __floats2half2_rn((v1.x - mean) * inv * g1.x + b1.x,
                                   (v1.y - mean) * inv * g1.y + b1.y);
    __half2 h3 = __floats2half2_rn((v1.z - mean) * inv * g1.z + b1.z,
                                   (v1.w - mean) * inv * g1.w + b1.w);

    __half2* q = (__half2*)(out + (size_t)row * kC);
    q[lane * 2]          = h0;
    q[lane * 2 + 1]      = h1;
    q[64 + lane * 2]     = h2;
    q[64 + lane * 2 + 1] = h3;
}

// ---------------- persistent fp16 GEMM (EPI 0,1,3) -------------------------
// out[M,N] = A[M,K] @ W[N,K]^T + epi. 128x128 tiles, persistent CTAs,
// 3-stage cp.async ring runs CONTINUOUSLY across tile boundaries.
constexpr int kAStr   = 40;
constexpr int kStageH = 128 * kAStr;
constexpr int kGemmSmem = 3 * kStageH * 2 * 2;  // 61440 bytes

template <int EPI>
__global__ __launch_bounds__(256, 2) void hgemm_persist(
    const __half* __restrict__ A, const __half* __restrict__ W,
    const float* __restrict__ bias, const float* __restrict__ res,
    void* __restrict__ out_v, int M, int N, int K, int nx, int lT)
{
    extern __shared__ __half sm[];
    __half* As = sm;
    __half* Bs = sm + 3 * kStageH;

    const int tid  = threadIdx.x;
    const int warp = tid >> 5;
    const int lane = tid & 31;
    const int grp  = lane >> 2;
    const int tig  = lane & 3;
    const int wm   = warp & 1;
    const int wn   = warp >> 1;

    const int T      = 1 << lT;            // K-stages per tile
    const int ntiles = (M >> 7) * nx;
    const int ntile_cta = (ntiles - blockIdx.x + gridDim.x - 1) / gridDim.x;
    const int total  = ntile_cta << lT;    // flat stage count for this CTA

    const int srow = tid >> 2;
    const int sch  = tid & 3;

    // prefetch flat stage u into ring slot
    auto prefetch = [&](int u, int slot) {
        int lt = u >> lT;
        int t  = u & (T - 1);
        int ti = blockIdx.x + lt * gridDim.x;
        int bm = (ti / nx) << 7;
        int bn = (ti % nx) << 7;
        const __half* Ag = A + (size_t)bm * K;
        const __half* Wg = W + (size_t)bn * K;
        int k0 = t << 5;
        #pragma unroll
        for (int u2 = 0; u2 < 2; u2++) {
            int row = srow + u2 * 64;
            cpa16(&As[slot * kStageH + row * kAStr + sch * 8],
                  Ag + (size_t)row * K + k0 + sch * 8);
            cpa16(&Bs[slot * kStageH + row * kAStr + sch * 8],
                  Wg + (size_t)row * K + k0 + sch * 8);
        }
        asm volatile("cp.async.commit_group;");
    };

    float c[4][4][4];
    #pragma unroll
    for (int i = 0; i < 4; i++)
        #pragma unroll
        for (int j = 0; j < 4; j++)
            #pragma unroll
            for (int r = 0; r < 4; r++) c[i][j][r] = 0.0f;

    prefetch(0, 0);
    prefetch(1, 1);

    const uint32_t smbA = (uint32_t)__cvta_generic_to_shared(As);
    const uint32_t smbB = (uint32_t)__cvta_generic_to_shared(Bs);
    const int aoff = (wm * 64 + (lane & 7) + ((lane >> 3) & 1) * 8) * kAStr
                   + ((lane >> 4) & 1) * 8;
    const int boff0 = (wn * 32 + ((lane >> 4) & 1) * 8 + (lane & 7)) * kAStr
                    + ((lane >> 3) & 1) * 8;
    const int boff1 = boff0 + 16 * kAStr;

    int cslot = 0, pslot = 2;
    for (int u = 0; u < total; u++) {
        if (u < total - 1) asm volatile("cp.async.wait_group 1;" ::: "memory");
        else               asm volatile("cp.async.wait_group 0;" ::: "memory");
        __syncthreads();

        const uint32_t abase = smbA + (uint32_t)(cslot * kStageH) * 2;
        const uint32_t bbase = smbB + (uint32_t)(cslot * kStageH) * 2;

        #pragma unroll
        for (int kb = 0; kb < 2; kb++) {
            uint32_t af[4][4];
            uint32_t bq0[4], bq1[4];
            #pragma unroll
            for (int i = 0; i < 4; i++)
                ldsm4(af[i], abase + (uint32_t)(aoff + i * 16 * kAStr + kb * 16) * 2);
            ldsm4(bq0, bbase + (uint32_t)(boff0 + kb * 16) * 2);
            ldsm4(bq1, bbase + (uint32_t)(boff1 + kb * 16) * 2);

            #pragma unroll
            for (int i = 0; i < 4; i++) {
                mma16816(c[i][0], af[i][0], af[i][1], af[i][2], af[i][3], bq0[0], bq0[1]);
                mma16816(c[i][1], af[i][0], af[i][1], af[i][2], af[i][3], bq0[2], bq0[3]);
                mma16816(c[i][2], af[i][0], af[i][1], af[i][2], af[i][3], bq1[0], bq1[1]);
                mma16816(c[i][3], af[i][0], af[i][1], af[i][2], af[i][3], bq1[2], bq1[3]);
            }
        }

        if (u + 2 < total) prefetch(u + 2, pslot);
        pslot = (pslot == 2) ? 0 : pslot + 1;
        cslot = (cslot == 2) ? 0 : cslot + 1;

        // tile finished -> epilogue + accumulator reset
        if ((u & (T - 1)) == T - 1) {
            int ti = blockIdx.x + (u >> lT) * gridDim.x;
            int bm = (ti / nx) << 7;
            int bn = (ti % nx) << 7;
            #pragma unroll
            for (int i = 0; i < 4; i++) {
                int mrow0 = bm + wm * 64 + i * 16 + grp;
                int mrow1 = mrow0 + 8;
                #pragma unroll
                for (int j = 0; j < 4; j++) {
                    int col = bn + wn * 32 + j * 8 + 2 * tig;
                    float2 bv = *(const float2*)&bias[col];
                    float v0 = c[i][j][0] + bv.x;
                    float v1 = c[i][j][1] + bv.y;
                    float v2 = c[i][j][2] + bv.x;
                    float v3 = c[i][j][3] + bv.y;
                    if (EPI == 0) {
                        __half* out = (__half*)out_v;
                        *(__half2*)&out[(size_t)mrow0 * N + col] = __floats2half2_rn(v0, v1);
                        *(__half2*)&out[(size_t)mrow1 * N + col] = __floats2half2_rn(v2, v3);
                    } else if (EPI == 1) {
                        __half* out = (__half*)out_v;
                        *(__half2*)&out[(size_t)mrow0 * N + col] =
                            __floats2half2_rn(gelu_exact(v0), gelu_exact(v1));
                        *(__half2*)&out[(size_t)mrow1 * N + col] =
                            __floats2half2_rn(gelu_exact(v2), gelu_exact(v3));
                    } else {
                        float* out = (float*)out_v;
                        float2 r0 = *(const float2*)&res[(size_t)mrow0 * 256 + col];
                        float2 r1 = *(const float2*)&res[(size_t)mrow1 * 256 + col];
                        *(float2*)&out[(size_t)mrow0 * N + col] = make_float2(v0 + r0.x, v1 + r0.y);
                        *(float2*)&out[(size_t)mrow1 * N + col] = make_float2(v2 + r1.x, v3 + r1.y);
                    }
                    c[i][j][0] = 0.0f; c[i][j][1] = 0.0f;
                    c[i][j][2] = 0.0f; c[i][j][3] = 0.0f;
                }
            }
        }
    }
}

// ---- fused out-proj + window-reverse + residual + LN2 (unchanged) ---------
constexpr int kFStageA = 64 * kAStr;    // 2560 halves
constexpr int kFStageB = 256 * kAStr;   // 10240 halves
constexpr int kFusedSmem = 3 * (kFStageA + kFStageB) * 2;  // 76800 bytes

__global__ __launch_bounds__(256, 2) void hgemm_oproj_ln2(
    const __half* __restrict__ A, const __half* __restrict__ W,
    const float* __restrict__ bias, const float* __restrict__ x,
    const float* __restrict__ g2, const float* __restrict__ b2,
    float* __restrict__ x2out, __half* __restrict__ lnout)
{
    extern __shared__ __half sm[];
    __half* As = sm;
    __half* Bs = sm + 3 * kFStageA;
    float*  red = (float*)sm;

    const int K = 256;
    const int bm   = blockIdx.x * 64;
    const int tid  = threadIdx.x;
    const int warp = tid >> 5;
    const int lane = tid & 31;
    const int grp  = lane >> 2;
    const int tig  = lane & 3;

    const __half* Ag = A + (size_t)bm * K;

    float c[4][4][4];
    #pragma unroll
    for (int i = 0; i < 4; i++)
        #pragma unroll
        for (int j = 0; j < 4; j++)
            #pragma unroll
            for (int r = 0; r < 4; r++) c[i][j][r] = 0.0f;

    const int T = K >> 5;  // 8

    const int arow = tid >> 2;
    const int ach  = tid & 3;

    #pragma unroll
    for (int st = 0; st < 2; st++) {
        int k0 = st << 5;
        cpa16(&As[st * kFStageA + arow * kAStr + ach * 8],
              Ag + (size_t)arow * K + k0 + ach * 8);
        #pragma unroll
        for (int u = 0; u < 4; u++) {
            int row = arow + u * 64;
            cpa16(&Bs[st * kFStageB + row * kAStr + ach * 8],
                  W + (size_t)row * K + k0 + ach * 8);
        }
        asm volatile("cp.async.commit_group;");
    }

    const uint32_t smbA = (uint32_t)__cvta_generic_to_shared(As);
    const uint32_t smbB = (uint32_t)__cvta_generic_to_shared(Bs);
    const int aoff = ((lane & 7) + ((lane >> 3) & 1) * 8) * kAStr
                   + ((lane >> 4) & 1) * 8;
    const int boff0 = (warp * 32 + ((lane >> 4) & 1) * 8 + (lane & 7)) * kAStr
                    + ((lane >> 3) & 1) * 8;
    const int boff1 = boff0 + 16 * kAStr;

    for (int t = 0; t < T; t++) {
        if (t < T - 1) asm volatile("cp.async.wait_group 1;" ::: "memory");
        else           asm volatile("cp.async.wait_group 0;" ::: "memory");
        __syncthreads();

        const int stage = t % 3;
        const uint32_t abase = smbA + (uint32_t)(stage * kFStageA) * 2;
        const uint32_t bbase = smbB + (uint32_t)(stage * kFStageB) * 2;

        #pragma unroll
        for (int kb = 0; kb < 2; kb++) {
            uint32_t af[4][4];
            uint32_t bq0[4], bq1[4];
            #pragma unroll
            for (int i = 0; i < 4; i++)
                ldsm4(af[i], abase + (uint32_t)(aoff + i * 16 * kAStr + kb * 16) * 2);
            ldsm4(bq0, bbase + (uint32_t)(boff0 + kb * 16) * 2);
            ldsm4(bq1, bbase + (uint32_t)(boff1 + kb * 16) * 2);

            #pragma unroll
            for (int i = 0; i < 4; i++) {
                mma16816(c[i][0], af[i][0], af[i][1], af[i][2], af[i][3], bq0[0], bq0[1]);
                mma16816(c[i][1], af[i][0], af[i][1], af[i][2], af[i][3], bq0[2], bq0[3]);
                mma16816(c[i][2], af[i][0], af[i][1], af[i][2], af[i][3], bq1[0], bq1[1]);
                mma16816(c[i][3], af[i][0], af[i][1], af[i][2], af[i][3], bq1[2], bq1[3]);
            }
        }

        if (t + 2 < T) {
            int k0 = (t + 2) << 5;
            int st = (t + 2) % 3;
            cpa16(&As[st * kFStageA + arow * kAStr + ach * 8],
                  Ag + (size_t)arow * K + k0 + ach * 8);
            #pragma unroll
            for (int u = 0; u < 4; u++) {
                int row = arow + u * 64;
                cpa16(&Bs[st * kFStageB + row * kAStr + ach * 8],
                      W + (size_t)row * K + k0 + ach * 8);
            }
            asm volatile("cp.async.commit_group;");
        }
    }

    // ---- epilogue pass 1: x2 = mma + bias + shortcut; write x2; stats ----
    int orow_[8];
    #pragma unroll
    for (int i = 0; i < 4; i++) {
        orow_[i * 2]     = win_to_nat(bm + i * 16 + grp);
        orow_[i * 2 + 1] = win_to_nat(bm + i * 16 + grp + 8);
    }

    float psum[8], psq[8];
    #pragma unroll
    for (int r = 0; r < 8; r++) { psum[r] = 0.0f; psq[r] = 0.0f; }

    #pragma unroll
    for (int i = 0; i < 4; i++) {
        #pragma unroll
        for (int j = 0; j < 4; j++) {
            int col = warp * 32 + j * 8 + 2 * tig;
            float2 bv = *(const float2*)&bias[col];
            float2 r0 = *(const float2*)&x[(size_t)orow_[i*2]   * 256 + col];
            float2 r1 = *(const float2*)&x[(size_t)orow_[i*2+1] * 256 + col];
            c[i][j][0] += bv.x + r0.x;
            c[i][j][1] += bv.y + r0.y;
            c[i][j][2] += bv.x + r1.x;
            c[i][j][3] += bv.y + r1.y;
            *(float2*)&x2out[(size_t)orow_[i*2]   * 256 + col] = make_float2(c[i][j][0], c[i][j][1]);
            *(float2*)&x2out[(size_t)orow_[i*2+1] * 256 + col] = make_float2(c[i][j][2], c[i][j][3]);
            psum[i*2]   += c[i][j][0] + c[i][j][1];
            psq[i*2]    += c[i][j][0]*c[i][j][0] + c[i][j][1]*c[i][j][1];
            psum[i*2+1] += c[i][j][2] + c[i][j][3];
            psq[i*2+1]  += c[i][j][2]*c[i][j][2] + c[i][j][3]*c[i][j][3];
        }
    }

    #pragma unroll
    for (int r = 0; r < 8; r++) {
        psum[r] += __shfl_xor_sync(0xffffffffu, psum[r], 1);
        psum[r] += __shfl_xor_sync(0xffffffffu, psum[r], 2);
        psq[r]  += __shfl_xor_sync(0xffffffffu, psq[r], 1);
        psq[r]  += __shfl_xor_sync(0xffffffffu, psq[r], 2);
    }

    __syncthreads();
    if (tig == 0) {
        #pragma unroll
        for (int i = 0; i < 4; i++) {
            int r0 = i * 16 + grp, r1 = r0 + 8;
            red[(r0 * 8 + warp) * 2]     = psum[i*2];
            red[(r0 * 8 + warp) * 2 + 1] = psq[i*2];
            red[(r1 * 8 + warp) * 2]     = psum[i*2+1];
            red[(r1 * 8 + warp) * 2 + 1] = psq[i*2+1];
        }
    }
    __syncthreads();

    if (tid < 64) {
        float s = 0.0f, sq = 0.0f;
        #pragma unroll
        for (int wdx = 0; wdx < 8; wdx++) {
            s  += red[(tid * 8 + wdx) * 2];
            sq += red[(tid * 8 + wdx) * 2 + 1];
        }
        float mean = s * (1.0f / 256.0f);
        float var  = sq * (1.0f / 256.0f) - mean * mean;
        red[1024 + tid * 2]     = mean;
        red[1024 + tid * 2 + 1] = rsqrtf(var + 1e-5f);
    }
    __syncthreads();

    #pragma unroll
    for (int i = 0; i < 4; i++) {
        int r0 = i * 16 + grp, r1 = r0 + 8;
        float m0 = red[1024 + r0 * 2], v0i = red[1024 + r0 * 2 + 1];
        float m1 = red[1024 + r1 * 2], v1i = red[1024 + r1 * 2 + 1];
        #pragma unroll
        for (int j = 0; j < 4; j++) {
            int col = warp * 32 + j * 8 + 2 * tig;
            float2 gg = *(const float2*)&g2[col];
            float2 bb = *(const float2*)&b2[col];
            *(__half2*)&lnout[(size_t)orow_[i*2] * 256 + col] =
                __floats2half2_rn((c[i][j][0] - m0) * v0i * gg.x + bb.x,
                                  (c[i][j][1] - m0) * v0i * gg.y + bb.y);
            *(__half2*)&lnout[(size_t)orow_[i*2+1] * 256 + col] =
                __floats2half2_rn((c[i][j][2] - m1) * v1i * gg.x + bb.x,
                                  (c[i][j][3] - m1) * v1i * gg.y + bb.y);
        }
    }
}

// ---------------- mma window attention (unchanged) ----------------
constexpr int kQKstr = 272;
constexpr int kVstr  = 264;
constexpr int kQoff  = 0;
constexpr int kKoff  = 64 * kQKstr;
constexpr int kVoff  = 2 * 64 * kQKstr;
constexpr int kAttnSmem = (kVoff + 64 * kVstr) * 2;

__global__ __launch_bounds__(256, 2) void attn_mma_kernel(
    const __half* __restrict__ qkv, __half* __restrict__ o)
{
    extern __shared__ __half sm[];
    const int tid  = threadIdx.x;
    const int win  = blockIdx.x;
    const int h    = tid >> 5;
    const int lane = tid & 31;
    const int grp  = lane >> 2;
    const int tig  = lane & 3;

    const __half* gbase = qkv + (size_t)win * 64 * 768;
    #pragma unroll
    for (int u = 0; u < 8; u++) {
        int idx = tid + u * 256;
        int t   = idx >> 5;
        int c8  = (idx & 31) << 3;
        const __half* gp = gbase + t * 768 + c8;
        *(uint4*)&sm[kQoff + t * kQKstr + c8] = *(const uint4*)gp;
        *(uint4*)&sm[kKoff + t * kQKstr + c8] = *(const uint4*)(gp + 256);
        *(uint4*)&sm[kVoff + t * kVstr  + c8] = *(const uint4*)(gp + 512);
    }
    __syncthreads();

    uint32_t bf[4][4][2];
    {
        const uint32_t smb = (uint32_t)__cvta_generic_to_shared(sm);
        int srow = (lane & 7) + ((lane >> 3) & 1) * 8;
        int dcol = h * 32 + (lane >> 4) * 8;
        #pragma unroll
        for (int kk = 0; kk < 4; kk++) {
            #pragma unroll
            for (int jp = 0; jp < 2; jp++) {
                uint32_t addr = smb +
                    (uint32_t)(kVoff + (kk * 16 + srow) * kVstr + dcol + jp * 16) * 2;
                uint32_t r[4];
                ldsm4t(r, addr);
                bf[kk][jp * 2 + 0][0] = r[0];
                bf[kk][jp * 2 + 0][1] = r[1];
                bf[kk][jp * 2 + 1][0] = r[2];
                bf[kk][jp * 2 + 1][1] = r[3];
            }
        }
    }

    const float scale = 0.17677669529663687f;

    #pragma unroll
    for (int i = 0; i < 4; i++) {
        float s[8][4];
        #pragma unroll
        for (int j = 0; j < 8; j++)
            #pragma unroll
            for (int r = 0; r < 4; r++) s[j][r] = 0.0f;

        #pragma unroll
        for (int kb = 0; kb < 2; kb++) {
            const int kcol = h * 32 + kb * 16 + tig * 4;
            const int r = i * 16 + grp;
            uint2 qlo = *(const uint2*)&sm[kQoff + r * kQKstr + kcol];
            uint2 qhi = *(const uint2*)&sm[kQoff + (r + 8) * kQKstr + kcol];
            #pragma unroll
            for (int j = 0; j < 8; j++) {
                uint2 kv = *(const uint2*)&sm[kKoff + (j * 8 + grp) * kQKstr + kcol];
                mma16816(s[j], qlo.x, qhi.x, qlo.y, qhi.y, kv.x, kv.y);
            }
        }

        float mx0 = -1e30f, mx1 = -1e30f;
        #pragma unroll
        for (int j = 0; j < 8; j++) {
            mx0 = fmaxf(mx0, fmaxf(s[j][0], s[j][1]));
            mx1 = fmaxf(mx1, fmaxf(s[j][2], s[j][3]));
        }
        mx0 = fmaxf(mx0, __shfl_xor_sync(0xffffffffu, mx0, 1));
        mx0 = fmaxf(mx0, __shfl_xor_sync(0xffffffffu, mx0, 2));
        mx1 = fmaxf(mx1, __shfl_xor_sync(0xffffffffu, mx1, 1));
        mx1 = fmaxf(mx1, __shfl_xor_sync(0xffffffffu, mx1, 2));

        float sum0 = 0.0f, sum1 = 0.0f;
        #pragma unroll
        for (int j = 0; j < 8; j++) {
            s[j][0] = __expf((s[j][0] - mx0) * scale);
            s[j][1] = __expf((s[j][1] - mx0) * scale);
            s[j][2] = __expf((s[j][2] - mx1) * scale);
            s[j][3] = __expf((s[j][3] - mx1) * scale);
            sum0 += s[j][0] + s[j][1];
            sum1 += s[j][2] + s[j][3];
        }
        sum0 += __shfl_xor_sync(0xffffffffu, sum0, 1);
        sum0 += __shfl_xor_sync(0xffffffffu, sum0, 2);
        sum1 += __shfl_xor_sync(0xffffffffu, sum1, 1);
        sum1 += __shfl_xor_sync(0xffffffffu, sum1, 2);
        float inv0 = 1.0f / sum0;
        float inv1 = 1.0f / sum1;

        uint32_t ph0[8], ph1[8];
        #pragma unroll
        for (int j = 0; j < 8; j++) {
            ph0[j] = packh2(s[j][0] * inv0, s[j][1] * inv0);
            ph1[j] = packh2(s[j][2] * inv1, s[j][3] * inv1);
        }

        float oa[4][4];
        #pragma unroll
        for (int jn = 0; jn < 4; jn++)
            #pragma unroll
            for (int r = 0; r < 4; r++) oa[jn][r] = 0.0f;

        #pragma unroll
        for (int kk = 0; kk < 4; kk++)
            #pragma unroll
            for (int jn = 0; jn < 4; jn++)
                mma16816(oa[jn], ph0[2 * kk], ph1[2 * kk],
                         ph0[2 * kk + 1], ph1[2 * kk + 1],
                         bf[kk][jn][0], bf[kk][jn][1]);

        int gr = win * 64 + i * 16 + grp;
        #pragma unroll
        for (int jn = 0; jn < 4; jn++) {
            int col = h * 32 + jn * 8 + tig * 2;
            *(__half2*)&o[(size_t)gr * 256 + col] =
                __floats2half2_rn(oa[jn][0], oa[jn][1]);
            *(__half2*)&o[(size_t)(gr + 8) * 256 + col] =
                __floats2half2_rn(oa[jn][2], oa[jn][3]);
        }
    }
}

// ---------------- launch ----------------
extern "C" void kernel_launch(void* const* d_in, const int* in_sizes, int n_in,
                              void* d_out, int out_size)
{
    const float* x     = (const float*)d_in[0];
    const float* ln1_g = (const float*)d_in[1];
    const float* ln1_b = (const float*)d_in[2];
    const float* in_w  = (const float*)d_in[3];
    const float* in_b  = (const float*)d_in[4];
    const float* out_w = (const float*)d_in[5];
    const float* out_b = (const float*)d_in[6];
    const float* ln2_g = (const float*)d_in[7];
    const float* ln2_b = (const float*)d_in[8];
    const float* w1    = (const float*)d_in[9];
    const float* b1    = (const float*)d_in[10];
    const float* w2    = (const float*)d_in[11];
    const float* b2    = (const float*)d_in[12];
    float* out = (float*)d_out;

    __half *big, *a, *bb, *w;
    float *cc;
    cudaGetSymbolAddress((void**)&big, g_big);
    cudaGetSymbolAddress((void**)&a,   g_a);
    cudaGetSymbolAddress((void**)&bb,  g_b);
    cudaGetSymbolAddress((void**)&cc,  g_c);
    cudaGetSymbolAddress((void**)&w,   g_w);

    __half* w_in  = w;
    __half* w_out = w + 196608;
    __half* w_1   = w + 262144;
    __half* w_2   = w + 524288;

    cudaFuncSetAttribute(attn_mma_kernel,
                         cudaFuncAttributeMaxDynamicSharedMemorySize, kAttnSmem);
    cudaFuncSetAttribute(hgemm_persist<0>,
                         cudaFuncAttributeMaxDynamicSharedMemorySize, kGemmSmem);
    cudaFuncSetAttribute(hgemm_persist<1>,
                         cudaFuncAttributeMaxDynamicSharedMemorySize, kGemmSmem);
    cudaFuncSetAttribute(hgemm_persist<3>,
                         cudaFuncAttributeMaxDynamicSharedMemorySize, kGemmSmem);
    cudaFuncSetAttribute(hgemm_oproj_ln2,
                         cudaFuncAttributeMaxDynamicSharedMemorySize, kFusedSmem);

    // 0) fp16 weights (single launch)
    cvtw_all<<<3072, 256>>>(in_w, out_w, w1, w2, w);
    // 1) LN1, natural -> windowed order, half out
    ln_kernel<<<kM / 8, 256>>>(x, ln1_g, ln1_b, a);
    // 2) QKV projection (persistent): M=kM, N=768, K=256, nx=6, T=8
    hgemm_persist<0><<<kPersistGrid, 256, kGemmSmem>>>(a, w_in, in_b, nullptr, big,
                                                       kM, 768, 256, 6, 3);
    // 3) windowed attention (tensor-core)
    attn_mma_kernel<<<kNWin, 256, kAttnSmem>>>(big, bb);
    // 4) out-proj + window-reverse + residual + LN2 (fused)
    hgemm_oproj_ln2<<<kM / 64, 256, kFusedSmem>>>(bb, w_out, out_b, x, ln2_g, ln2_b, cc, a);
    // 5) MLP up + exact GELU (persistent): N=1024, K=256, nx=8, T=8
    hgemm_persist<1><<<kPersistGrid, 256, kGemmSmem>>>(a, w_1, b1, nullptr, big,
                                                       kM, 1024, 256, 8, 3);
    // 6) MLP down + residual (persistent): N=256, K=1024, nx=2, T=32
    hgemm_persist<3><<<kPersistGrid, 256, kGemmSmem>>>(big, w_2, b2, cc, out,
                                                       kM, 256, 1024, 2, 5);
}

// round 12
// speedup vs baseline: 1.6473x; 1.6473x over previous
#include <cuda_runtime.h>
#include <cuda_fp16.h>
#include <cstdint>
#include <math.h>

// ---------------- problem constants ----------------
constexpr int kB    = 8;
constexpr int kGrid = 128;
constexpr int kNtok = kGrid * kGrid;
constexpr int kC    = 256;
constexpr int kM    = kB * kNtok;     // 131072 tokens
constexpr int kHid  = 1024;
constexpr int kNWin = kB * 256;       // 2048 windows

// ---------------- scratch ----------------
__device__ __half g_big[(size_t)kM * kHid];
__device__ __half g_a  [(size_t)kM * kC];
__device__ __half g_b  [(size_t)kM * kC];
__device__ float  g_c  [(size_t)kM * kC];
__device__ __half g_w  [786432];

__device__ __forceinline__ int win_to_nat(int m) {
    int win = m >> 6;
    int t   = m & 63;
    int b   = win >> 8;
    int wi  = win & 255;
    int row = ((wi >> 4) << 3) + (t >> 3);
    int col = ((wi & 15) << 3) + (t & 7);
    return b * kNtok + row * kGrid + col;
}

__device__ __forceinline__ float gelu_exact(float x) {
    return 0.5f * x * (1.0f + erff(x * 0.70710678118654752f));
}

__device__ __forceinline__ void cpa16(__half* s, const __half* g) {
    uint32_t sa = (uint32_t)__cvta_generic_to_shared(s);
    asm volatile("cp.async.cg.shared.global [%0], [%1], 16;" :: "r"(sa), "l"(g));
}

__device__ __forceinline__ void mma16816(float* c, uint32_t a0, uint32_t a1,
                                         uint32_t a2, uint32_t a3,
                                         uint32_t b0, uint32_t b1) {
    asm volatile(
        "mma.sync.aligned.m16n8k16.row.col.f32.f16.f16.f32 "
        "{%0,%1,%2,%3}, {%4,%5,%6,%7}, {%8,%9}, {%0,%1,%2,%3};"
        : "+f"(c[0]), "+f"(c[1]), "+f"(c[2]), "+f"(c[3])
        : "r"(a0), "r"(a1), "r"(a2), "r"(a3), "r"(b0), "r"(b1));
}

__device__ __forceinline__ void ldsm4(uint32_t* r, uint32_t addr) {
    asm volatile("ldmatrix.sync.aligned.m8n8.x4.shared.b16 {%0,%1,%2,%3}, [%4];"
        : "=r"(r[0]), "=r"(r[1]), "=r"(r[2]), "=r"(r[3]) : "r"(addr));
}
__device__ __forceinline__ void ldsm4t(uint32_t* r, uint32_t addr) {
    asm volatile("ldmatrix.sync.aligned.m8n8.x4.trans.shared.b16 {%0,%1,%2,%3}, [%4];"
        : "=r"(r[0]), "=r"(r[1]), "=r"(r[2]), "=r"(r[3]) : "r"(addr));
}

__device__ __forceinline__ uint32_t packh2(float x, float y) {
    __half2 h = __floats2half2_rn(x, y);
    return *(uint32_t*)&h;
}

// ---------------- fp16 weight conversion (single launch) ----------------
__global__ __launch_bounds__(256) void cvtw_all(
    const float* __restrict__ in_w, const float* __restrict__ out_w,
    const float* __restrict__ w1, const float* __restrict__ w2,
    __half* __restrict__ o)
{
    int i = blockIdx.x * 256 + threadIdx.x;
    const float* src;
    int off;
    if (i < 196608)      { src = in_w;  off = i; }
    else if (i < 262144) { src = out_w; off = i - 196608; }
    else if (i < 524288) { src = w1;    off = i - 262144; }
    else                 { src = w2;    off = i - 524288; }
    o[i] = __float2half(src[off]);
}

// ---------------- LayerNorm (LN1): natural -> windowed, half out ----------
__global__ __launch_bounds__(256) void ln_kernel(
    const float* __restrict__ in, const float* __restrict__ g,
    const float* __restrict__ b, __half* __restrict__ out)
{
    int row  = blockIdx.x * 8 + (threadIdx.x >> 5);
    int lane = threadIdx.x & 31;
    int src  = win_to_nat(row);

    const float4* p = (const float4*)(in + (size_t)src * kC);
    float4 v0 = p[lane];
    float4 v1 = p[lane + 32];

    float s  = v0.x + v0.y + v0.z + v0.w + v1.x + v1.y + v1.z + v1.w;
    float s2 = v0.x*v0.x + v0.y*v0.y + v0.z*v0.z + v0.w*v0.w
             + v1.x*v1.x + v1.y*v1.y + v1.z*v1.z + v1.w*v1.w;
    #pragma unroll
    for (int off = 16; off > 0; off >>= 1) {
        s  += __shfl_xor_sync(0xffffffffu, s,  off);
        s2 += __shfl_xor_sync(0xffffffffu, s2, off);
    }
    float mean = s * (1.0f / kC);
    float var  = s2 * (1.0f / kC) - mean * mean;
    float inv  = rsqrtf(var + 1e-5f);

    const float4* gp = (const float4*)g;
    const float4* bp = (const float4*)b;
    float4 g0 = gp[lane], g1 = gp[lane + 32];
    float4 b0 = bp[lane], b1 = bp[lane + 32];

    __half2 h0 = __floats2half2_rn((v0.x - mean) * inv * g0.x + b0.x,
                                   (v0.y - mean) * inv * g0.y + b0.y);
    __half2 h1 = __floats2half2_rn((v0.z - mean) * inv * g0.z + b0.z,
                                   (v0.w - mean) * inv * g0.w + b0.w);
    __half2 h2 = __floats2half2_rn((v1.x - mean) * inv * g1.x + b1.x,
                                   (v1.y - mean) * inv * g1.y + b1.y);
    __half2 h3 = __floats2half2_rn((v1.z - mean) * inv * g1.z + b1.z,
                                   (v1.w - mean) * inv * g1.w + b1.w);

    __half2* q = (__half2*)(out + (size_t)row * kC);
    q[lane * 2]          = h0;
    q[lane * 2 + 1]      = h1;
    q[64 + lane * 2]     = h2;
    q[64 + lane * 2 + 1] = h3;
}

// ---------------- fp16 GEMM: BK=64, 3-stage cp.async + ldmatrix -----------
// out[M,N] = A[M,K] @ W[N,K]^T + epi. 128x128 tile, 8 warps (2x4).
// SMEM row stride 72 halves (144B): 16B-group rotation 16 -> conflict-free.
constexpr int kGStr   = 72;
constexpr int kGStage = 128 * kGStr;            // 9216 halves per stage/matrix
constexpr int kGemmSmem = 3 * kGStage * 2 * 2;  // 110592 bytes

template <int EPI>
__global__ __launch_bounds__(256, 2) void hgemm_kernel(
    const __half* __restrict__ A, const __half* __restrict__ W,
    const float* __restrict__ bias, const float* __restrict__ res,
    void* __restrict__ out_v, int M, int N, int K)
{
    extern __shared__ __half sm[];
    __half* As = sm;
    __half* Bs = sm + 3 * kGStage;

    const int bm   = blockIdx.y * 128;
    const int bn   = blockIdx.x * 128;
    const int tid  = threadIdx.x;
    const int warp = tid >> 5;
    const int lane = tid & 31;
    const int grp  = lane >> 2;
    const int tig  = lane & 3;
    const int wm   = warp & 1;
    const int wn   = warp >> 1;

    const __half* Ag = A + (size_t)bm * K;
    const __half* Wg = W + (size_t)bn * K;

    float c[4][4][4];
    #pragma unroll
    for (int i = 0; i < 4; i++)
        #pragma unroll
        for (int j = 0; j < 4; j++)
            #pragma unroll
            for (int r = 0; r < 4; r++) c[i][j][r] = 0.0f;

    const int T = K >> 6;  // BK = 64

    const int srow = tid >> 3;   // 0..31
    const int sch  = tid & 7;    // 16B chunk within 64-half row

    auto stage_load = [&](int slot, int k0) {
        #pragma unroll
        for (int u = 0; u < 4; u++) {
            int row = srow + u * 32;
            cpa16(&As[slot * kGStage + row * kGStr + sch * 8],
                  Ag + (size_t)row * K + k0 + sch * 8);
            cpa16(&Bs[slot * kGStage + row * kGStr + sch * 8],
                  Wg + (size_t)row * K + k0 + sch * 8);
        }
        asm volatile("cp.async.commit_group;");
    };

    stage_load(0, 0);
    stage_load(1, 64);

    const uint32_t smbA = (uint32_t)__cvta_generic_to_shared(As);
    const uint32_t smbB = (uint32_t)__cvta_generic_to_shared(Bs);
    const int aoff = (wm * 64 + (lane & 7) + ((lane >> 3) & 1) * 8) * kGStr
                   + ((lane >> 4) & 1) * 8;
    const int boff0 = (wn * 32 + ((lane >> 4) & 1) * 8 + (lane & 7)) * kGStr
                    + ((lane >> 3) & 1) * 8;
    const int boff1 = boff0 + 16 * kGStr;

    for (int t = 0; t < T; t++) {
        if (t < T - 1) asm volatile("cp.async.wait_group 1;" ::: "memory");
        else           asm volatile("cp.async.wait_group 0;" ::: "memory");
        __syncthreads();

        const int stage = t % 3;
        const uint32_t abase = smbA + (uint32_t)(stage * kGStage) * 2;
        const uint32_t bbase = smbB + (uint32_t)(stage * kGStage) * 2;

        #pragma unroll
        for (int kb = 0; kb < 4; kb++) {
            uint32_t af[4][4];
            uint32_t bq0[4], bq1[4];
            #pragma unroll
            for (int i = 0; i < 4; i++)
                ldsm4(af[i], abase + (uint32_t)(aoff + i * 16 * kGStr + kb * 16) * 2);
            ldsm4(bq0, bbase + (uint32_t)(boff0 + kb * 16) * 2);
            ldsm4(bq1, bbase + (uint32_t)(boff1 + kb * 16) * 2);

            #pragma unroll
            for (int i = 0; i < 4; i++) {
                mma16816(c[i][0], af[i][0], af[i][1], af[i][2], af[i][3], bq0[0], bq0[1]);
                mma16816(c[i][1], af[i][0], af[i][1], af[i][2], af[i][3], bq0[2], bq0[3]);
                mma16816(c[i][2], af[i][0], af[i][1], af[i][2], af[i][3], bq1[0], bq1[1]);
                mma16816(c[i][3], af[i][0], af[i][1], af[i][2], af[i][3], bq1[2], bq1[3]);
            }
        }

        if (t + 2 < T) stage_load((t + 2) % 3, (t + 2) << 6);
    }

    // ---- epilogue ----
    #pragma unroll
    for (int i = 0; i < 4; i++) {
        int mrow0 = bm + wm * 64 + i * 16 + grp;
        int mrow1 = mrow0 + 8;
        #pragma unroll
        for (int j = 0; j < 4; j++) {
            int col = bn + wn * 32 + j * 8 + 2 * tig;
            float2 bv = *(const float2*)&bias[col];
            float v0 = c[i][j][0] + bv.x;
            float v1 = c[i][j][1] + bv.y;
            float v2 = c[i][j][2] + bv.x;
            float v3 = c[i][j][3] + bv.y;
            if (EPI == 0) {
                __half* out = (__half*)out_v;
                *(__half2*)&out[(size_t)mrow0 * N + col] = __floats2half2_rn(v0, v1);
                *(__half2*)&out[(size_t)mrow1 * N + col] = __floats2half2_rn(v2, v3);
            } else if (EPI == 1) {
                __half* out = (__half*)out_v;
                *(__half2*)&out[(size_t)mrow0 * N + col] =
                    __floats2half2_rn(gelu_exact(v0), gelu_exact(v1));
                *(__half2*)&out[(size_t)mrow1 * N + col] =
                    __floats2half2_rn(gelu_exact(v2), gelu_exact(v3));
            } else {
                float* out = (float*)out_v;
                float2 r0 = *(const float2*)&res[(size_t)mrow0 * 256 + col];
                float2 r1 = *(const float2*)&res[(size_t)mrow1 * 256 + col];
                *(float2*)&out[(size_t)mrow0 * N + col] = make_float2(v0 + r0.x, v1 + r0.y);
                *(float2*)&out[(size_t)mrow1 * N + col] = make_float2(v2 + r1.x, v3 + r1.y);
            }
        }
    }
}

// ---- fused out-proj + window-reverse + residual + LN2 (R10, unchanged) ----
constexpr int kAStr   = 40;
constexpr int kFStageA = 64 * kAStr;    // 2560 halves
constexpr int kFStageB = 256 * kAStr;   // 10240 halves
constexpr int kFusedSmem = 3 * (kFStageA + kFStageB) * 2;  // 76800 bytes

__global__ __launch_bounds__(256, 2) void hgemm_oproj_ln2(
    const __half* __restrict__ A, const __half* __restrict__ W,
    const float* __restrict__ bias, const float* __restrict__ x,
    const float* __restrict__ g2, const float* __restrict__ b2,
    float* __restrict__ x2out, __half* __restrict__ lnout)
{
    extern __shared__ __half sm[];
    __half* As = sm;
    __half* Bs = sm + 3 * kFStageA;
    float*  red = (float*)sm;

    const int K = 256;
    const int bm   = blockIdx.x * 64;
    const int tid  = threadIdx.x;
    const int warp = tid >> 5;
    const int lane = tid & 31;
    const int grp  = lane >> 2;
    const int tig  = lane & 3;

    const __half* Ag = A + (size_t)bm * K;

    float c[4][4][4];
    #pragma unroll
    for (int i = 0; i < 4; i++)
        #pragma unroll
        for (int j = 0; j < 4; j++)
            #pragma unroll
            for (int r = 0; r < 4; r++) c[i][j][r] = 0.0f;

    const int T = K >> 5;  // 8

    const int arow = tid >> 2;
    const int ach  = tid & 3;

    #pragma unroll
    for (int st = 0; st < 2; st++) {
        int k0 = st << 5;
        cpa16(&As[st * kFStageA + arow * kAStr + ach * 8],
              Ag + (size_t)arow * K + k0 + ach * 8);
        #pragma unroll
        for (int u = 0; u < 4; u++) {
            int row = arow + u * 64;
            cpa16(&Bs[st * kFStageB + row * kAStr + ach * 8],
                  W + (size_t)row * K + k0 + ach * 8);
        }
        asm volatile("cp.async.commit_group;");
    }

    const uint32_t smbA = (uint32_t)__cvta_generic_to_shared(As);
    const uint32_t smbB = (uint32_t)__cvta_generic_to_shared(Bs);
    const int aoff = ((lane & 7) + ((lane >> 3) & 1) * 8) * kAStr
                   + ((lane >> 4) & 1) * 8;
    const int boff0 = (warp * 32 + ((lane >> 4) & 1) * 8 + (lane & 7)) * kAStr
                    + ((lane >> 3) & 1) * 8;
    const int boff1 = boff0 + 16 * kAStr;

    for (int t = 0; t < T; t++) {
        if (t < T - 1) asm volatile("cp.async.wait_group 1;" ::: "memory");
        else           asm volatile("cp.async.wait_group 0;" ::: "memory");
        __syncthreads();

        const int stage = t % 3;
        const uint32_t abase = smbA + (uint32_t)(stage * kFStageA) * 2;
        const uint32_t bbase = smbB + (uint32_t)(stage * kFStageB) * 2;

        #pragma unroll
        for (int kb = 0; kb < 2; kb++) {
            uint32_t af[4][4];
            uint32_t bq0[4], bq1[4];
            #pragma unroll
            for (int i = 0; i < 4; i++)
                ldsm4(af[i], abase + (uint32_t)(aoff + i * 16 * kAStr + kb * 16) * 2);
            ldsm4(bq0, bbase + (uint32_t)(boff0 + kb * 16) * 2);
            ldsm4(bq1, bbase + (uint32_t)(boff1 + kb * 16) * 2);

            #pragma unroll
            for (int i = 0; i < 4; i++) {
                mma16816(c[i][0], af[i][0], af[i][1], af[i][2], af[i][3], bq0[0], bq0[1]);
                mma16816(c[i][1], af[i][0], af[i][1], af[i][2], af[i][3], bq0[2], bq0[3]);
                mma16816(c[i][2], af[i][0], af[i][1], af[i][2], af[i][3], bq1[0], bq1[1]);
                mma16816(c[i][3], af[i][0], af[i][1], af[i][2], af[i][3], bq1[2], bq1[3]);
            }
        }

        if (t + 2 < T) {
            int k0 = (t + 2) << 5;
            int st = (t + 2) % 3;
            cpa16(&As[st * kFStageA + arow * kAStr + ach * 8],
                  Ag + (size_t)arow * K + k0 + ach * 8);
            #pragma unroll
            for (int u = 0; u < 4; u++) {
                int row = arow + u * 64;
                cpa16(&Bs[st * kFStageB + row * kAStr + ach * 8],
                      W + (size_t)row * K + k0 + ach * 8);
            }
            asm volatile("cp.async.commit_group;");
        }
    }

    int orow_[8];
    #pragma unroll
    for (int i = 0; i < 4; i++) {
        orow_[i * 2]     = win_to_nat(bm + i * 16 + grp);
        orow_[i * 2 + 1] = win_to_nat(bm + i * 16 + grp + 8);
    }

    float psum[8], psq[8];
    #pragma unroll
    for (int r = 0; r < 8; r++) { psum[r] = 0.0f; psq[r] = 0.0f; }

    #pragma unroll
    for (int i = 0; i < 4; i++) {
        #pragma unroll
        for (int j = 0; j < 4; j++) {
            int col = warp * 32 + j * 8 + 2 * tig;
            float2 bv = *(const float2*)&bias[col];
            float2 r0 = *(const float2*)&x[(size_t)orow_[i*2]   * 256 + col];
            float2 r1 = *(const float2*)&x[(size_t)orow_[i*2+1] * 256 + col];
            c[i][j][0] += bv.x + r0.x;
            c[i][j][1] += bv.y + r0.y;
            c[i][j][2] += bv.x + r1.x;
            c[i][j][3] += bv.y + r1.y;
            *(float2*)&x2out[(size_t)orow_[i*2]   * 256 + col] = make_float2(c[i][j][0], c[i][j][1]);
            *(float2*)&x2out[(size_t)orow_[i*2+1] * 256 + col] = make_float2(c[i][j][2], c[i][j][3]);
            psum[i*2]   += c[i][j][0] + c[i][j][1];
            psq[i*2]    += c[i][j][0]*c[i][j][0] + c[i][j][1]*c[i][j][1];
            psum[i*2+1] += c[i][j][2] + c[i][j][3];
            psq[i*2+1]  += c[i][j][2]*c[i][j][2] + c[i][j][3]*c[i][j][3];
        }
    }

    #pragma unroll
    for (int r = 0; r < 8; r++) {
        psum[r] += __shfl_xor_sync(0xffffffffu, psum[r], 1);
        psum[r] += __shfl_xor_sync(0xffffffffu, psum[r], 2);
        psq[r]  += __shfl_xor_sync(0xffffffffu, psq[r], 1);
        psq[r]  += __shfl_xor_sync(0xffffffffu, psq[r], 2);
    }

    __syncthreads();
    if (tig == 0) {
        #pragma unroll
        for (int i = 0; i < 4; i++) {
            int r0 = i * 16 + grp, r1 = r0 + 8;
            red[(r0 * 8 + warp) * 2]     = psum[i*2];
            red[(r0 * 8 + warp) * 2 + 1] = psq[i*2];
            red[(r1 * 8 + warp) * 2]     = psum[i*2+1];
            red[(r1 * 8 + warp) * 2 + 1] = psq[i*2+1];
        }
    }
    __syncthreads();

    if (tid < 64) {
        float s = 0.0f, sq = 0.0f;
        #pragma unroll
        for (int wdx = 0; wdx < 8; wdx++) {
            s  += red[(tid * 8 + wdx) * 2];
            sq += red[(tid * 8 + wdx) * 2 + 1];
        }
        float mean = s * (1.0f / 256.0f);
        float var  = sq * (1.0f / 256.0f) - mean * mean;
        red[1024 + tid * 2]     = mean;
        red[1024 + tid * 2 + 1] = rsqrtf(var + 1e-5f);
    }
    __syncthreads();

    #pragma unroll
    for (int i = 0; i < 4; i++) {
        int r0 = i * 16 + grp, r1 = r0 + 8;
        float m0 = red[1024 + r0 * 2], v0i = red[1024 + r0 * 2 + 1];
        float m1 = red[1024 + r1 * 2], v1i = red[1024 + r1 * 2 + 1];
        #pragma unroll
        for (int j = 0; j < 4; j++) {
            int col = warp * 32 + j * 8 + 2 * tig;
            float2 gg = *(const float2*)&g2[col];
            float2 bb = *(const float2*)&b2[col];
            *(__half2*)&lnout[(size_t)orow_[i*2] * 256 + col] =
                __floats2half2_rn((c[i][j][0] - m0) * v0i * gg.x + bb.x,
                                  (c[i][j][1] - m0) * v0i * gg.y + bb.y);
            *(__half2*)&lnout[(size_t)orow_[i*2+1] * 256 + col] =
                __floats2half2_rn((c[i][j][2] - m1) * v1i * gg.x + bb.x,
                                  (c[i][j][3] - m1) * v1i * gg.y + bb.y);
        }
    }
}

// ---------------- mma window attention v3: ldmatrix Q/K, stride 264 -------
constexpr int kQKstr = 264;
constexpr int kVstr  = 264;
constexpr int kQoff  = 0;
constexpr int kKoff  = 64 * kQKstr;
constexpr int kVoff  = 2 * 64 * kQKstr;
constexpr int kAttnSmem = (kVoff + 64 * kVstr) * 2;   // 101376 B

__global__ __launch_bounds__(256, 2) void attn_mma_kernel(
    const __half* __restrict__ qkv, __half* __restrict__ o)
{
    extern __shared__ __half sm[];
    const int tid  = threadIdx.x;
    const int win  = blockIdx.x;
    const int h    = tid >> 5;
    const int lane = tid & 31;
    const int grp  = lane >> 2;
    const int tig  = lane & 3;

    const __half* gbase = qkv + (size_t)win * 64 * 768;
    #pragma unroll
    for (int u = 0; u < 8; u++) {
        int idx = tid + u * 256;
        int t   = idx >> 5;
        int c8  = (idx & 31) << 3;
        const __half* gp = gbase + t * 768 + c8;
        *(uint4*)&sm[kQoff + t * kQKstr + c8] = *(const uint4*)gp;
        *(uint4*)&sm[kKoff + t * kQKstr + c8] = *(const uint4*)(gp + 256);
        *(uint4*)&sm[kVoff + t * kVstr  + c8] = *(const uint4*)(gp + 512);
    }
    __syncthreads();

    const uint32_t smb = (uint32_t)__cvta_generic_to_shared(sm);

    // ---- V fragments (resident, ldmatrix.trans) ----
    uint32_t bf[4][4][2];
    {
        int srow = (lane & 7) + ((lane >> 3) & 1) * 8;
        int dcol = h * 32 + (lane >> 4) * 8;
        #pragma unroll
        for (int kk = 0; kk < 4; kk++) {
            #pragma unroll
            for (int jp = 0; jp < 2; jp++) {
                uint32_t addr = smb +
                    (uint32_t)(kVoff + (kk * 16 + srow) * kVstr + dcol + jp * 16) * 2;
                uint32_t r[4];
                ldsm4t(r, addr);
                bf[kk][jp * 2 + 0][0] = r[0];
                bf[kk][jp * 2 + 0][1] = r[1];
                bf[kk][jp * 2 + 1][0] = r[2];
                bf[kk][jp * 2 + 1][1] = r[3];
            }
        }
    }

    // ldmatrix lane addressing for Q (A-frag) and K (B-frag)
    const int qrow = (lane & 7) + ((lane >> 3) & 1) * 8;        // 0..15
    const int qcol = h * 32 + ((lane >> 4) & 1) * 8;
    const int krow = ((lane >> 4) & 1) * 8 + (lane & 7);        // within n16
    const int kcolb = h * 32 + ((lane >> 3) & 1) * 8;

    const float scale = 0.17677669529663687f;

    #pragma unroll
    for (int i = 0; i < 4; i++) {
        float s[8][4];
        #pragma unroll
        for (int j = 0; j < 8; j++)
            #pragma unroll
            for (int r = 0; r < 4; r++) s[j][r] = 0.0f;

        #pragma unroll
        for (int kb = 0; kb < 2; kb++) {
            uint32_t qf[4];
            ldsm4(qf, smb + (uint32_t)(kQoff + (i * 16 + qrow) * kQKstr
                                       + qcol + kb * 16) * 2);
            #pragma unroll
            for (int jj = 0; jj < 4; jj++) {
                uint32_t kq[4];
                ldsm4(kq, smb + (uint32_t)(kKoff + (jj * 16 + krow) * kQKstr
                                           + kcolb + kb * 16) * 2);
                mma16816(s[2 * jj],     qf[0], qf[1], qf[2], qf[3], kq[0], kq[1]);
                mma16816(s[2 * jj + 1], qf[0], qf[1], qf[2], qf[3], kq[2], kq[3]);
            }
        }

        float mx0 = -1e30f, mx1 = -1e30f;
        #pragma unroll
        for (int j = 0; j < 8; j++) {
            mx0 = fmaxf(mx0, fmaxf(s[j][0], s[j][1]));
            mx1 = fmaxf(mx1, fmaxf(s[j][2], s[j][3]));
        }
        mx0 = fmaxf(mx0, __shfl_xor_sync(0xffffffffu, mx0, 1));
        mx0 = fmaxf(mx0, __shfl_xor_sync(0xffffffffu, mx0, 2));
        mx1 = fmaxf(mx1, __shfl_xor_sync(0xffffffffu, mx1, 1));
        mx1 = fmaxf(mx1, __shfl_xor_sync(0xffffffffu, mx1, 2));

        float sum0 = 0.0f, sum1 = 0.0f;
        #pragma unroll
        for (int j = 0; j < 8; j++) {
            s[j][0] = __expf((s[j][0] - mx0) * scale);
            s[j][1] = __expf((s[j][1] - mx0) * scale);
            s[j][2] = __expf((s[j][2] - mx1) * scale);
            s[j][3] = __expf((s[j][3] - mx1) * scale);
            sum0 += s[j][0] + s[j][1];
            sum1 += s[j][2] + s[j][3];
        }
        sum0 += __shfl_xor_sync(0xffffffffu, sum0, 1);
        sum0 += __shfl_xor_sync(0xffffffffu, sum0, 2);
        sum1 += __shfl_xor_sync(0xffffffffu, sum1, 1);
        sum1 += __shfl_xor_sync(0xffffffffu, sum1, 2);
        float inv0 = 1.0f / sum0;
        float inv1 = 1.0f / sum1;

        uint32_t ph0[8], ph1[8];
        #pragma unroll
        for (int j = 0; j < 8; j++) {
            ph0[j] = packh2(s[j][0] * inv0, s[j][1] * inv0);
            ph1[j] = packh2(s[j][2] * inv1, s[j][3] * inv1);
        }

        float oa[4][4];
        #pragma unroll
        for (int jn = 0; jn < 4; jn++)
            #pragma unroll
            for (int r = 0; r < 4; r++) oa[jn][r] = 0.0f;

        #pragma unroll
        for (int kk = 0; kk < 4; kk++)
            #pragma unroll
            for (int jn = 0; jn < 4; jn++)
                mma16816(oa[jn], ph0[2 * kk], ph1[2 * kk],
                         ph0[2 * kk + 1], ph1[2 * kk + 1],
                         bf[kk][jn][0], bf[kk][jn][1]);

        int gr = win * 64 + i * 16 + grp;
        #pragma unroll
        for (int jn = 0; jn < 4; jn++) {
            int col = h * 32 + jn * 8 + tig * 2;
            *(__half2*)&o[(size_t)gr * 256 + col] =
                __floats2half2_rn(oa[jn][0], oa[jn][1]);
            *(__half2*)&o[(size_t)(gr + 8) * 256 + col] =
                __floats2half2_rn(oa[jn][2], oa[jn][3]);
        }
    }
}

// ---------------- launch ----------------
extern "C" void kernel_launch(void* const* d_in, const int* in_sizes, int n_in,
                              void* d_out, int out_size)
{
    const float* x     = (const float*)d_in[0];
    const float* ln1_g = (const float*)d_in[1];
    const float* ln1_b = (const float*)d_in[2];
    const float* in_w  = (const float*)d_in[3];
    const float* in_b  = (const float*)d_in[4];
    const float* out_w = (const float*)d_in[5];
    const float* out_b = (const float*)d_in[6];
    const float* ln2_g = (const float*)d_in[7];
    const float* ln2_b = (const float*)d_in[8];
    const float* w1    = (const float*)d_in[9];
    const float* b1    = (const float*)d_in[10];
    const float* w2    = (const float*)d_in[11];
    const float* b2    = (const float*)d_in[12];
    float* out = (float*)d_out;

    __half *big, *a, *bb, *w;
    float *cc;
    cudaGetSymbolAddress((void**)&big, g_big);
    cudaGetSymbolAddress((void**)&a,   g_a);
    cudaGetSymbolAddress((void**)&bb,  g_b);
    cudaGetSymbolAddress((void**)&cc,  g_c);
    cudaGetSymbolAddress((void**)&w,   g_w);

    __half* w_in  = w;
    __half* w_out = w + 196608;
    __half* w_1   = w + 262144;
    __half* w_2   = w + 524288;

    cudaFuncSetAttribute(attn_mma_kernel,
                         cudaFuncAttributeMaxDynamicSharedMemorySize, kAttnSmem);
    cudaFuncSetAttribute(hgemm_kernel<0>,
                         cudaFuncAttributeMaxDynamicSharedMemorySize, kGemmSmem);
    cudaFuncSetAttribute(hgemm_kernel<1>,
                         cudaFuncAttributeMaxDynamicSharedMemorySize, kGemmSmem);
    cudaFuncSetAttribute(hgemm_kernel<3>,
                         cudaFuncAttributeMaxDynamicSharedMemorySize, kGemmSmem);
    cudaFuncSetAttribute(hgemm_oproj_ln2,
                         cudaFuncAttributeMaxDynamicSharedMemorySize, kFusedSmem);

    // 0) fp16 weights (single launch)
    cvtw_all<<<3072, 256>>>(in_w, out_w, w1, w2, w);
    // 1) LN1, natural -> windowed order, half out
    ln_kernel<<<kM / 8, 256>>>(x, ln1_g, ln1_b, a);
    // 2) QKV projection (BK=64)
    hgemm_kernel<0><<<dim3(6, kM / 128), 256, kGemmSmem>>>(a, w_in, in_b, nullptr, big, kM, 768, kC);
    // 3) windowed attention (tensor-core, ldmatrix everywhere)
    attn_mma_kernel<<<kNWin, 256, kAttnSmem>>>(big, bb);
    // 4) out-proj + window-reverse + residual + LN2 (fused)
    hgemm_oproj_ln2<<<kM / 64, 256, kFusedSmem>>>(bb, w_out, out_b, x, ln2_g, ln2_b, cc, a);
    // 5) MLP up + exact GELU (BK=64)
    hgemm_kernel<1><<<dim3(8, kM / 128), 256, kGemmSmem>>>(a, w_1, b1, nullptr, big, kM, kHid, kC);
    // 6) MLP down + residual -> fp32 final output (BK=64, T=16)
    hgemm_kernel<3><<<dim3(2, kM / 128), 256, kGemmSmem>>>(big, w_2, b2, cc, out, kM, kC, kHid);
}

// round 13
// speedup vs baseline: 1.7096x; 1.0378x over previous
#include <cuda_runtime.h>
#include <cuda_fp16.h>
#include <cstdint>
#include <math.h>

// ---------------- problem constants ----------------
constexpr int kB    = 8;
constexpr int kGrid = 128;
constexpr int kNtok = kGrid * kGrid;
constexpr int kC    = 256;
constexpr int kM    = kB * kNtok;     // 131072 tokens
constexpr int kHid  = 1024;
constexpr int kNWin = kB * 256;       // 2048 windows

// ---------------- scratch ----------------
__device__ __half g_big[(size_t)kM * kHid];
__device__ __half g_a  [(size_t)kM * kC];
__device__ __half g_b  [(size_t)kM * kC];
__device__ float  g_c  [(size_t)kM * kC];
__device__ __half g_w  [786432];

__device__ __forceinline__ int win_to_nat(int m) {
    int win = m >> 6;
    int t   = m & 63;
    int b   = win >> 8;
    int wi  = win & 255;
    int row = ((wi >> 4) << 3) + (t >> 3);
    int col = ((wi & 15) << 3) + (t & 7);
    return b * kNtok + row * kGrid + col;
}

__device__ __forceinline__ float gelu_exact(float x) {
    return 0.5f * x * (1.0f + erff(x * 0.70710678118654752f));
}

__device__ __forceinline__ void cpa16(__half* s, const __half* g) {
    uint32_t sa = (uint32_t)__cvta_generic_to_shared(s);
    asm volatile("cp.async.cg.shared.global [%0], [%1], 16;" :: "r"(sa), "l"(g));
}

__device__ __forceinline__ void mma16816(float* c, uint32_t a0, uint32_t a1,
                                         uint32_t a2, uint32_t a3,
                                         uint32_t b0, uint32_t b1) {
    asm volatile(
        "mma.sync.aligned.m16n8k16.row.col.f32.f16.f16.f32 "
        "{%0,%1,%2,%3}, {%4,%5,%6,%7}, {%8,%9}, {%0,%1,%2,%3};"
        : "+f"(c[0]), "+f"(c[1]), "+f"(c[2]), "+f"(c[3])
        : "r"(a0), "r"(a1), "r"(a2), "r"(a3), "r"(b0), "r"(b1));
}

__device__ __forceinline__ void ldsm4(uint32_t* r, uint32_t addr) {
    asm volatile("ldmatrix.sync.aligned.m8n8.x4.shared.b16 {%0,%1,%2,%3}, [%4];"
        : "=r"(r[0]), "=r"(r[1]), "=r"(r[2]), "=r"(r[3]) : "r"(addr));
}
__device__ __forceinline__ void ldsm4t(uint32_t* r, uint32_t addr) {
    asm volatile("ldmatrix.sync.aligned.m8n8.x4.trans.shared.b16 {%0,%1,%2,%3}, [%4];"
        : "=r"(r[0]), "=r"(r[1]), "=r"(r[2]), "=r"(r[3]) : "r"(addr));
}

__device__ __forceinline__ uint32_t packh2(float x, float y) {
    __half2 h = __floats2half2_rn(x, y);
    return *(uint32_t*)&h;
}

// ---------------- fp16 weight conversion (single launch) ----------------
__global__ __launch_bounds__(256) void cvtw_all(
    const float* __restrict__ in_w, const float* __restrict__ out_w,
    const float* __restrict__ w1, const float* __restrict__ w2,
    __half* __restrict__ o)
{
    int i = blockIdx.x * 256 + threadIdx.x;
    const float* src;
    int off;
    if (i < 196608)      { src = in_w;  off = i; }
    else if (i < 262144) { src = out_w; off = i - 196608; }
    else if (i < 524288) { src = w1;    off = i - 262144; }
    else                 { src = w2;    off = i - 524288; }
    o[i] = __float2half(src[off]);
}

// ---------------- LayerNorm (LN1): natural -> windowed, half out ----------
__global__ __launch_bounds__(256) void ln_kernel(
    const float* __restrict__ in, const float* __restrict__ g,
    const float* __restrict__ b, __half* __restrict__ out)
{
    int row  = blockIdx.x * 8 + (threadIdx.x >> 5);
    int lane = threadIdx.x & 31;
    int src  = win_to_nat(row);

    const float4* p = (const float4*)(in + (size_t)src * kC);
    float4 v0 = p[lane];
    float4 v1 = p[lane + 32];

    float s  = v0.x + v0.y + v0.z + v0.w + v1.x + v1.y + v1.z + v1.w;
    float s2 = v0.x*v0.x + v0.y*v0.y + v0.z*v0.z + v0.w*v0.w
             + v1.x*v1.x + v1.y*v1.y + v1.z*v1.z + v1.w*v1.w;
    #pragma unroll
    for (int off = 16; off > 0; off >>= 1) {
        s  += __shfl_xor_sync(0xffffffffu, s,  off);
        s2 += __shfl_xor_sync(0xffffffffu, s2, off);
    }
    float mean = s * (1.0f / kC);
    float var  = s2 * (1.0f / kC) - mean * mean;
    float inv  = rsqrtf(var + 1e-5f);

    const float4* gp = (const float4*)g;
    const float4* bp = (const float4*)b;
    float4 g0 = gp[lane], g1 = gp[lane + 32];
    float4 b0 = bp[lane], b1 = bp[lane + 32];

    __half2 h0 = __floats2half2_rn((v0.x - mean) * inv * g0.x + b0.x,
                                   (v0.y - mean) * inv * g0.y + b0.y);
    __half2 h1 = __floats2half2_rn((v0.z - mean) * inv * g0.z + b0.z,
                                   (v0.w - mean) * inv * g0.w + b0.w);
    __half2 h2 = __floats2half2_rn((v1.x - mean) * inv * g1.x + b1.x,
                                   (v1.y - mean) * inv * g1.y + b1.y);
    __half2 h3 = __floats2half2_rn((v1.z - mean) * inv * g1.z + b1.z,
                                   (v1.w - mean) * inv * g1.w + b1.w);

    __half2* q = (__half2*)(out + (size_t)row * kC);
    q[lane * 2]          = h0;
    q[lane * 2 + 1]      = h1;
    q[64 + lane * 2]     = h2;
    q[64 + lane * 2 + 1] = h3;
}

// ---------------- fp16 GEMM: BK=64, 3-stage ring, compile-time K/N --------
constexpr int kGStr   = 72;
constexpr int kGStage = 128 * kGStr;            // 9216 halves per stage/matrix
constexpr int kGemmSmem = 3 * kGStage * 2 * 2;  // 110592 bytes

template <int EPI, int KK, int NN>
__global__ __launch_bounds__(256, 2) void hgemm_kernel(
    const __half* __restrict__ A, const __half* __restrict__ W,
    const float* __restrict__ bias, const float* __restrict__ res,
    void* __restrict__ out_v)
{
    extern __shared__ __half sm[];
    __half* As = sm;
    __half* Bs = sm + 3 * kGStage;

    const int bm   = blockIdx.y * 128;
    const int bn   = blockIdx.x * 128;
    const int tid  = threadIdx.x;
    const int warp = tid >> 5;
    const int lane = tid & 31;
    const int grp  = lane >> 2;
    const int tig  = lane & 3;
    const int wm   = warp & 1;
    const int wn   = warp >> 1;

    const __half* Ag = A + (size_t)bm * KK;
    const __half* Wg = W + (size_t)bn * KK;

    float c[4][4][4];
    #pragma unroll
    for (int i = 0; i < 4; i++)
        #pragma unroll
        for (int j = 0; j < 4; j++)
            #pragma unroll
            for (int r = 0; r < 4; r++) c[i][j][r] = 0.0f;

    constexpr int T = KK >> 6;  // BK = 64

    const int srow = tid >> 3;   // 0..31
    const int sch  = tid & 7;    // 16B chunk within 64-half row

    auto stage_load = [&](int slot, int k0) {
        #pragma unroll
        for (int u = 0; u < 4; u++) {
            int row = srow + u * 32;
            cpa16(&As[slot * kGStage + row * kGStr + sch * 8],
                  Ag + (size_t)row * KK + k0 + sch * 8);
            cpa16(&Bs[slot * kGStage + row * kGStr + sch * 8],
                  Wg + (size_t)row * KK + k0 + sch * 8);
        }
        asm volatile("cp.async.commit_group;");
    };

    stage_load(0, 0);
    stage_load(1, 64);

    const uint32_t smbA = (uint32_t)__cvta_generic_to_shared(As);
    const uint32_t smbB = (uint32_t)__cvta_generic_to_shared(Bs);
    const int aoff = (wm * 64 + (lane & 7) + ((lane >> 3) & 1) * 8) * kGStr
                   + ((lane >> 4) & 1) * 8;
    const int boff0 = (wn * 32 + ((lane >> 4) & 1) * 8 + (lane & 7)) * kGStr
                    + ((lane >> 3) & 1) * 8;
    const int boff1 = boff0 + 16 * kGStr;

    for (int t = 0; t < T; t++) {
        if (t < T - 1) asm volatile("cp.async.wait_group 1;" ::: "memory");
        else           asm volatile("cp.async.wait_group 0;" ::: "memory");
        __syncthreads();

        // prefetch t+2 FIRST: its slot holds t-1's data, consumed before this
        // barrier -> safe, and the loads overlap both compute-t and compute-t+1.
        if (t + 2 < T) stage_load((t + 2) % 3, (t + 2) << 6);

        const int stage = t % 3;
        const uint32_t abase = smbA + (uint32_t)(stage * kGStage) * 2;
        const uint32_t bbase = smbB + (uint32_t)(stage * kGStage) * 2;

        #pragma unroll
        for (int kb = 0; kb < 4; kb++) {
            uint32_t af[4][4];
            uint32_t bq0[4], bq1[4];
            #pragma unroll
            for (int i = 0; i < 4; i++)
                ldsm4(af[i], abase + (uint32_t)(aoff + i * 16 * kGStr + kb * 16) * 2);
            ldsm4(bq0, bbase + (uint32_t)(boff0 + kb * 16) * 2);
            ldsm4(bq1, bbase + (uint32_t)(boff1 + kb * 16) * 2);

            #pragma unroll
            for (int i = 0; i < 4; i++) {
                mma16816(c[i][0], af[i][0], af[i][1], af[i][2], af[i][3], bq0[0], bq0[1]);
                mma16816(c[i][1], af[i][0], af[i][1], af[i][2], af[i][3], bq0[2], bq0[3]);
                mma16816(c[i][2], af[i][0], af[i][1], af[i][2], af[i][3], bq1[0], bq1[1]);
                mma16816(c[i][3], af[i][0], af[i][1], af[i][2], af[i][3], bq1[2], bq1[3]);
            }
        }
    }

    // ---- epilogue ----
    #pragma unroll
    for (int i = 0; i < 4; i++) {
        int mrow0 = bm + wm * 64 + i * 16 + grp;
        int mrow1 = mrow0 + 8;
        #pragma unroll
        for (int j = 0; j < 4; j++) {
            int col = bn + wn * 32 + j * 8 + 2 * tig;
            float2 bv = *(const float2*)&bias[col];
            float v0 = c[i][j][0] + bv.x;
            float v1 = c[i][j][1] + bv.y;
            float v2 = c[i][j][2] + bv.x;
            float v3 = c[i][j][3] + bv.y;
            if (EPI == 0) {
                __half* out = (__half*)out_v;
                *(__half2*)&out[(size_t)mrow0 * NN + col] = __floats2half2_rn(v0, v1);
                *(__half2*)&out[(size_t)mrow1 * NN + col] = __floats2half2_rn(v2, v3);
            } else if (EPI == 1) {
                __half* out = (__half*)out_v;
                *(__half2*)&out[(size_t)mrow0 * NN + col] =
                    __floats2half2_rn(gelu_exact(v0), gelu_exact(v1));
                *(__half2*)&out[(size_t)mrow1 * NN + col] =
                    __floats2half2_rn(gelu_exact(v2), gelu_exact(v3));
            } else {
                float* out = (float*)out_v;
                float2 r0 = *(const float2*)&res[(size_t)mrow0 * 256 + col];
                float2 r1 = *(const float2*)&res[(size_t)mrow1 * 256 + col];
                *(float2*)&out[(size_t)mrow0 * NN + col] = make_float2(v0 + r0.x, v1 + r0.y);
                *(float2*)&out[(size_t)mrow1 * NN + col] = make_float2(v2 + r1.x, v3 + r1.y);
            }
        }
    }
}

// ---- fused out-proj + window-reverse + residual + LN2 (unchanged) ---------
constexpr int kAStr   = 40;
constexpr int kFStageA = 64 * kAStr;    // 2560 halves
constexpr int kFStageB = 256 * kAStr;   // 10240 halves
constexpr int kFusedSmem = 3 * (kFStageA + kFStageB) * 2;  // 76800 bytes

__global__ __launch_bounds__(256, 2) void hgemm_oproj_ln2(
    const __half* __restrict__ A, const __half* __restrict__ W,
    const float* __restrict__ bias, const float* __restrict__ x,
    const float* __restrict__ g2, const float* __restrict__ b2,
    float* __restrict__ x2out, __half* __restrict__ lnout)
{
    extern __shared__ __half sm[];
    __half* As = sm;
    __half* Bs = sm + 3 * kFStageA;
    float*  red = (float*)sm;

    const int K = 256;
    const int bm   = blockIdx.x * 64;
    const int tid  = threadIdx.x;
    const int warp = tid >> 5;
    const int lane = tid & 31;
    const int grp  = lane >> 2;
    const int tig  = lane & 3;

    const __half* Ag = A + (size_t)bm * K;

    float c[4][4][4];
    #pragma unroll
    for (int i = 0; i < 4; i++)
        #pragma unroll
        for (int j = 0; j < 4; j++)
            #pragma unroll
            for (int r = 0; r < 4; r++) c[i][j][r] = 0.0f;

    const int T = K >> 5;  // 8

    const int arow = tid >> 2;
    const int ach  = tid & 3;

    #pragma unroll
    for (int st = 0; st < 2; st++) {
        int k0 = st << 5;
        cpa16(&As[st * kFStageA + arow * kAStr + ach * 8],
              Ag + (size_t)arow * K + k0 + ach * 8);
        #pragma unroll
        for (int u = 0; u < 4; u++) {
            int row = arow + u * 64;
            cpa16(&Bs[st * kFStageB + row * kAStr + ach * 8],
                  W + (size_t)row * K + k0 + ach * 8);
        }
        asm volatile("cp.async.commit_group;");
    }

    const uint32_t smbA = (uint32_t)__cvta_generic_to_shared(As);
    const uint32_t smbB = (uint32_t)__cvta_generic_to_shared(Bs);
    const int aoff = ((lane & 7) + ((lane >> 3) & 1) * 8) * kAStr
                   + ((lane >> 4) & 1) * 8;
    const int boff0 = (warp * 32 + ((lane >> 4) & 1) * 8 + (lane & 7)) * kAStr
                    + ((lane >> 3) & 1) * 8;
    const int boff1 = boff0 + 16 * kAStr;

    for (int t = 0; t < T; t++) {
        if (t < T - 1) asm volatile("cp.async.wait_group 1;" ::: "memory");
        else           asm volatile("cp.async.wait_group 0;" ::: "memory");
        __syncthreads();

        const int stage = t % 3;
        const uint32_t abase = smbA + (uint32_t)(stage * kFStageA) * 2;
        const uint32_t bbase = smbB + (uint32_t)(stage * kFStageB) * 2;

        #pragma unroll
        for (int kb = 0; kb < 2; kb++) {
            uint32_t af[4][4];
            uint32_t bq0[4], bq1[4];
            #pragma unroll
            for (int i = 0; i < 4; i++)
                ldsm4(af[i], abase + (uint32_t)(aoff + i * 16 * kAStr + kb * 16) * 2);
            ldsm4(bq0, bbase + (uint32_t)(boff0 + kb * 16) * 2);
            ldsm4(bq1, bbase + (uint32_t)(boff1 + kb * 16) * 2);

            #pragma unroll
            for (int i = 0; i < 4; i++) {
                mma16816(c[i][0], af[i][0], af[i][1], af[i][2], af[i][3], bq0[0], bq0[1]);
                mma16816(c[i][1], af[i][0], af[i][1], af[i][2], af[i][3], bq0[2], bq0[3]);
                mma16816(c[i][2], af[i][0], af[i][1], af[i][2], af[i][3], bq1[0], bq1[1]);
                mma16816(c[i][3], af[i][0], af[i][1], af[i][2], af[i][3], bq1[2], bq1[3]);
            }
        }

        if (t + 2 < T) {
            int k0 = (t + 2) << 5;
            int st = (t + 2) % 3;
            cpa16(&As[st * kFStageA + arow * kAStr + ach * 8],
                  Ag + (size_t)arow * K + k0 + ach * 8);
            #pragma unroll
            for (int u = 0; u < 4; u++) {
                int row = arow + u * 64;
                cpa16(&Bs[st * kFStageB + row * kAStr + ach * 8],
                      W + (size_t)row * K + k0 + ach * 8);
            }
            asm volatile("cp.async.commit_group;");
        }
    }

    int orow_[8];
    #pragma unroll
    for (int i = 0; i < 4; i++) {
        orow_[i * 2]     = win_to_nat(bm + i * 16 + grp);
        orow_[i * 2 + 1] = win_to_nat(bm + i * 16 + grp + 8);
    }

    float psum[8], psq[8];
    #pragma unroll
    for (int r = 0; r < 8; r++) { psum[r] = 0.0f; psq[r] = 0.0f; }

    #pragma unroll
    for (int i = 0; i < 4; i++) {
        #pragma unroll
        for (int j = 0; j < 4; j++) {
            int col = warp * 32 + j * 8 + 2 * tig;
            float2 bv = *(const float2*)&bias[col];
            float2 r0 = *(const float2*)&x[(size_t)orow_[i*2]   * 256 + col];
            float2 r1 = *(const float2*)&x[(size_t)orow_[i*2+1] * 256 + col];
            c[i][j][0] += bv.x + r0.x;
            c[i][j][1] += bv.y + r0.y;
            c[i][j][2] += bv.x + r1.x;
            c[i][j][3] += bv.y + r1.y;
            *(float2*)&x2out[(size_t)orow_[i*2]   * 256 + col] = make_float2(c[i][j][0], c[i][j][1]);
            *(float2*)&x2out[(size_t)orow_[i*2+1] * 256 + col] = make_float2(c[i][j][2], c[i][j][3]);
            psum[i*2]   += c[i][j][0] + c[i][j][1];
            psq[i*2]    += c[i][j][0]*c[i][j][0] + c[i][j][1]*c[i][j][1];
            psum[i*2+1] += c[i][j][2] + c[i][j][3];
            psq[i*2+1]  += c[i][j][2]*c[i][j][2] + c[i][j][3]*c[i][j][3];
        }
    }

    #pragma unroll
    for (int r = 0; r < 8; r++) {
        psum[r] += __shfl_xor_sync(0xffffffffu, psum[r], 1);
        psum[r] += __shfl_xor_sync(0xffffffffu, psum[r], 2);
        psq[r]  += __shfl_xor_sync(0xffffffffu, psq[r], 1);
        psq[r]  += __shfl_xor_sync(0xffffffffu, psq[r], 2);
    }

    __syncthreads();
    if (tig == 0) {
        #pragma unroll
        for (int i = 0; i < 4; i++) {
            int r0 = i * 16 + grp, r1 = r0 + 8;
            red[(r0 * 8 + warp) * 2]     = psum[i*2];
            red[(r0 * 8 + warp) * 2 + 1] = psq[i*2];
            red[(r1 * 8 + warp) * 2]     = psum[i*2+1];
            red[(r1 * 8 + warp) * 2 + 1] = psq[i*2+1];
        }
    }
    __syncthreads();

    if (tid < 64) {
        float s = 0.0f, sq = 0.0f;
        #pragma unroll
        for (int wdx = 0; wdx < 8; wdx++) {
            s  += red[(tid * 8 + wdx) * 2];
            sq += red[(tid * 8 + wdx) * 2 + 1];
        }
        float mean = s * (1.0f / 256.0f);
        float var  = sq * (1.0f / 256.0f) - mean * mean;
        red[1024 + tid * 2]     = mean;
        red[1024 + tid * 2 + 1] = rsqrtf(var + 1e-5f);
    }
    __syncthreads();

    #pragma unroll
    for (int i = 0; i < 4; i++) {
        int r0 = i * 16 + grp, r1 = r0 + 8;
        float m0 = red[1024 + r0 * 2], v0i = red[1024 + r0 * 2 + 1];
        float m1 = red[1024 + r1 * 2], v1i = red[1024 + r1 * 2 + 1];
        #pragma unroll
        for (int j = 0; j < 4; j++) {
            int col = warp * 32 + j * 8 + 2 * tig;
            float2 gg = *(const float2*)&g2[col];
            float2 bb = *(const float2*)&b2[col];
            *(__half2*)&lnout[(size_t)orow_[i*2] * 256 + col] =
                __floats2half2_rn((c[i][j][0] - m0) * v0i * gg.x + bb.x,
                                  (c[i][j][1] - m0) * v0i * gg.y + bb.y);
            *(__half2*)&lnout[(size_t)orow_[i*2+1] * 256 + col] =
                __floats2half2_rn((c[i][j][2] - m1) * v1i * gg.x + bb.x,
                                  (c[i][j][3] - m1) * v1i * gg.y + bb.y);
        }
    }
}

// ---------------- mma window attention (unchanged from R12) ----------------
constexpr int kQKstr = 264;
constexpr int kVstr  = 264;
constexpr int kQoff  = 0;
constexpr int kKoff  = 64 * kQKstr;
constexpr int kVoff  = 2 * 64 * kQKstr;
constexpr int kAttnSmem = (kVoff + 64 * kVstr) * 2;   // 101376 B

__global__ __launch_bounds__(256, 2) void attn_mma_kernel(
    const __half* __restrict__ qkv, __half* __restrict__ o)
{
    extern __shared__ __half sm[];
    const int tid  = threadIdx.x;
    const int win  = blockIdx.x;
    const int h    = tid >> 5;
    const int lane = tid & 31;
    const int grp  = lane >> 2;
    const int tig  = lane & 3;

    const __half* gbase = qkv + (size_t)win * 64 * 768;
    #pragma unroll
    for (int u = 0; u < 8; u++) {
        int idx = tid + u * 256;
        int t   = idx >> 5;
        int c8  = (idx & 31) << 3;
        const __half* gp = gbase + t * 768 + c8;
        *(uint4*)&sm[kQoff + t * kQKstr + c8] = *(const uint4*)gp;
        *(uint4*)&sm[kKoff + t * kQKstr + c8] = *(const uint4*)(gp + 256);
        *(uint4*)&sm[kVoff + t * kVstr  + c8] = *(const uint4*)(gp + 512);
    }
    __syncthreads();

    const uint32_t smb = (uint32_t)__cvta_generic_to_shared(sm);

    uint32_t bf[4][4][2];
    {
        int srow = (lane & 7) + ((lane >> 3) & 1) * 8;
        int dcol = h * 32 + (lane >> 4) * 8;
        #pragma unroll
        for (int kk = 0; kk < 4; kk++) {
            #pragma unroll
            for (int jp = 0; jp < 2; jp++) {
                uint32_t addr = smb +
                    (uint32_t)(kVoff + (kk * 16 + srow) * kVstr + dcol + jp * 16) * 2;
                uint32_t r[4];
                ldsm4t(r, addr);
                bf[kk][jp * 2 + 0][0] = r[0];
                bf[kk][jp * 2 + 0][1] = r[1];
                bf[kk][jp * 2 + 1][0] = r[2];
                bf[kk][jp * 2 + 1][1] = r[3];
            }
        }
    }

    const int qrow = (lane & 7) + ((lane >> 3) & 1) * 8;
    const int qcol = h * 32 + ((lane >> 4) & 1) * 8;
    const int krow = ((lane >> 4) & 1) * 8 + (lane & 7);
    const int kcolb = h * 32 + ((lane >> 3) & 1) * 8;

    const float scale = 0.17677669529663687f;

    #pragma unroll
    for (int i = 0; i < 4; i++) {
        float s[8][4];
        #pragma unroll
        for (int j = 0; j < 8; j++)
            #pragma unroll
            for (int r = 0; r < 4; r++) s[j][r] = 0.0f;

        #pragma unroll
        for (int kb = 0; kb < 2; kb++) {
            uint32_t qf[4];
            ldsm4(qf, smb + (uint32_t)(kQoff + (i * 16 + qrow) * kQKstr
                                       + qcol + kb * 16) * 2);
            #pragma unroll
            for (int jj = 0; jj < 4; jj++) {
                uint32_t kq[4];
                ldsm4(kq, smb + (uint32_t)(kKoff + (jj * 16 + krow) * kQKstr
                                           + kcolb + kb * 16) * 2);
                mma16816(s[2 * jj],     qf[0], qf[1], qf[2], qf[3], kq[0], kq[1]);
                mma16816(s[2 * jj + 1], qf[0], qf[1], qf[2], qf[3], kq[2], kq[3]);
            }
        }

        float mx0 = -1e30f, mx1 = -1e30f;
        #pragma unroll
        for (int j = 0; j < 8; j++) {
            mx0 = fmaxf(mx0, fmaxf(s[j][0], s[j][1]));
            mx1 = fmaxf(mx1, fmaxf(s[j][2], s[j][3]));
        }
        mx0 = fmaxf(mx0, __shfl_xor_sync(0xffffffffu, mx0, 1));
        mx0 = fmaxf(mx0, __shfl_xor_sync(0xffffffffu, mx0, 2));
        mx1 = fmaxf(mx1, __shfl_xor_sync(0xffffffffu, mx1, 1));
        mx1 = fmaxf(mx1, __shfl_xor_sync(0xffffffffu, mx1, 2));

        float sum0 = 0.0f, sum1 = 0.0f;
        #pragma unroll
        for (int j = 0; j < 8; j++) {
            s[j][0] = __expf((s[j][0] - mx0) * scale);
            s[j][1] = __expf((s[j][1] - mx0) * scale);
            s[j][2] = __expf((s[j][2] - mx1) * scale);
            s[j][3] = __expf((s[j][3] - mx1) * scale);
            sum0 += s[j][0] + s[j][1];
            sum1 += s[j][2] + s[j][3];
        }
        sum0 += __shfl_xor_sync(0xffffffffu, sum0, 1);
        sum0 += __shfl_xor_sync(0xffffffffu, sum0, 2);
        sum1 += __shfl_xor_sync(0xffffffffu, sum1, 1);
        sum1 += __shfl_xor_sync(0xffffffffu, sum1, 2);
        float inv0 = 1.0f / sum0;
        float inv1 = 1.0f / sum1;

        uint32_t ph0[8], ph1[8];
        #pragma unroll
        for (int j = 0; j < 8; j++) {
            ph0[j] = packh2(s[j][0] * inv0, s[j][1] * inv0);
            ph1[j] = packh2(s[j][2] * inv1, s[j][3] * inv1);
        }

        float oa[4][4];
        #pragma unroll
        for (int jn = 0; jn < 4; jn++)
            #pragma unroll
            for (int r = 0; r < 4; r++) oa[jn][r] = 0.0f;

        #pragma unroll
        for (int kk = 0; kk < 4; kk++)
            #pragma unroll
            for (int jn = 0; jn < 4; jn++)
                mma16816(oa[jn], ph0[2 * kk], ph1[2 * kk],
                         ph0[2 * kk + 1], ph1[2 * kk + 1],
                         bf[kk][jn][0], bf[kk][jn][1]);

        int gr = win * 64 + i * 16 + grp;
        #pragma unroll
        for (int jn = 0; jn < 4; jn++) {
            int col = h * 32 + jn * 8 + tig * 2;
            *(__half2*)&o[(size_t)gr * 256 + col] =
                __floats2half2_rn(oa[jn][0], oa[jn][1]);
            *(__half2*)&o[(size_t)(gr + 8) * 256 + col] =
                __floats2half2_rn(oa[jn][2], oa[jn][3]);
        }
    }
}

// ---------------- launch ----------------
extern "C" void kernel_launch(void* const* d_in, const int* in_sizes, int n_in,
                              void* d_out, int out_size)
{
    const float* x     = (const float*)d_in[0];
    const float* ln1_g = (const float*)d_in[1];
    const float* ln1_b = (const float*)d_in[2];
    const float* in_w  = (const float*)d_in[3];
    const float* in_b  = (const float*)d_in[4];
    const float* out_w = (const float*)d_in[5];
    const float* out_b = (const float*)d_in[6];
    const float* ln2_g = (const float*)d_in[7];
    const float* ln2_b = (const float*)d_in[8];
    const float* w1    = (const float*)d_in[9];
    const float* b1    = (const float*)d_in[10];
    const float* w2    = (const float*)d_in[11];
    const float* b2    = (const float*)d_in[12];
    float* out = (float*)d_out;

    __half *big, *a, *bb, *w;
    float *cc;
    cudaGetSymbolAddress((void**)&big, g_big);
    cudaGetSymbolAddress((void**)&a,   g_a);
    cudaGetSymbolAddress((void**)&bb,  g_b);
    cudaGetSymbolAddress((void**)&cc,  g_c);
    cudaGetSymbolAddress((void**)&w,   g_w);

    __half* w_in  = w;
    __half* w_out = w + 196608;
    __half* w_1   = w + 262144;
    __half* w_2   = w + 524288;

    cudaFuncSetAttribute(attn_mma_kernel,
                         cudaFuncAttributeMaxDynamicSharedMemorySize, kAttnSmem);
    cudaFuncSetAttribute((hgemm_kernel<0, 256, 768>),
                         cudaFuncAttributeMaxDynamicSharedMemorySize, kGemmSmem);
    cudaFuncSetAttribute((hgemm_kernel<1, 256, 1024>),
                         cudaFuncAttributeMaxDynamicSharedMemorySize, kGemmSmem);
    cudaFuncSetAttribute((hgemm_kernel<3, 1024, 256>),
                         cudaFuncAttributeMaxDynamicSharedMemorySize, kGemmSmem);
    cudaFuncSetAttribute(hgemm_oproj_ln2,
                         cudaFuncAttributeMaxDynamicSharedMemorySize, kFusedSmem);

    // 0) fp16 weights (single launch)
    cvtw_all<<<3072, 256>>>(in_w, out_w, w1, w2, w);
    // 1) LN1, natural -> windowed order, half out
    ln_kernel<<<kM / 8, 256>>>(x, ln1_g, ln1_b, a);
    // 2) QKV projection (BK=64, compile-time K/N)
    hgemm_kernel<0, 256, 768><<<dim3(6, kM / 128), 256, kGemmSmem>>>(a, w_in, in_b, nullptr, big);
    // 3) windowed attention (tensor-core)
    attn_mma_kernel<<<kNWin, 256, kAttnSmem>>>(big, bb);
    // 4) out-proj + window-reverse + residual + LN2 (fused)
    hgemm_oproj_ln2<<<kM / 64, 256, kFusedSmem>>>(bb, w_out, out_b, x, ln2_g, ln2_b, cc, a);
    // 5) MLP up + exact GELU
    hgemm_kernel<1, 256, 1024><<<dim3(8, kM / 128), 256, kGemmSmem>>>(a, w_1, b1, nullptr, big);
    // 6) MLP down + residual -> fp32 final output
    hgemm_kernel<3, 1024, 256><<<dim3(2, kM / 128), 256, kGemmSmem>>>(big, w_2, b2, cc, out);
}

// round 14
// speedup vs baseline: 1.7474x; 1.0221x over previous
#include <cuda_runtime.h>
#include <cuda_fp16.h>
#include <cstdint>
#include <math.h>

// ---------------- problem constants ----------------
constexpr int kB    = 8;
constexpr int kGrid = 128;
constexpr int kNtok = kGrid * kGrid;
constexpr int kC    = 256;
constexpr int kM    = kB * kNtok;     // 131072 tokens
constexpr int kHid  = 1024;
constexpr int kNWin = kB * 256;       // 2048 windows

// ---------------- scratch ----------------
__device__ __half g_big[(size_t)kM * kHid];
__device__ __half g_a  [(size_t)kM * kC];
__device__ __half g_b  [(size_t)kM * kC];
__device__ float  g_c  [(size_t)kM * kC];
__device__ __half g_w  [786432];

__device__ __forceinline__ int win_to_nat(int m) {
    int win = m >> 6;
    int t   = m & 63;
    int b   = win >> 8;
    int wi  = win & 255;
    int row = ((wi >> 4) << 3) + (t >> 3);
    int col = ((wi & 15) << 3) + (t & 7);
    return b * kNtok + row * kGrid + col;
}

__device__ __forceinline__ float gelu_exact(float x) {
    return 0.5f * x * (1.0f + erff(x * 0.70710678118654752f));
}

__device__ __forceinline__ void cpa16(__half* s, const __half* g) {
    uint32_t sa = (uint32_t)__cvta_generic_to_shared(s);
    asm volatile("cp.async.cg.shared.global [%0], [%1], 16;" :: "r"(sa), "l"(g));
}

__device__ __forceinline__ void mma16816(float* c, uint32_t a0, uint32_t a1,
                                         uint32_t a2, uint32_t a3,
                                         uint32_t b0, uint32_t b1) {
    asm volatile(
        "mma.sync.aligned.m16n8k16.row.col.f32.f16.f16.f32 "
        "{%0,%1,%2,%3}, {%4,%5,%6,%7}, {%8,%9}, {%0,%1,%2,%3};"
        : "+f"(c[0]), "+f"(c[1]), "+f"(c[2]), "+f"(c[3])
        : "r"(a0), "r"(a1), "r"(a2), "r"(a3), "r"(b0), "r"(b1));
}

__device__ __forceinline__ void ldsm4(uint32_t* r, uint32_t addr) {
    asm volatile("ldmatrix.sync.aligned.m8n8.x4.shared.b16 {%0,%1,%2,%3}, [%4];"
        : "=r"(r[0]), "=r"(r[1]), "=r"(r[2]), "=r"(r[3]) : "r"(addr));
}
__device__ __forceinline__ void ldsm4t(uint32_t* r, uint32_t addr) {
    asm volatile("ldmatrix.sync.aligned.m8n8.x4.trans.shared.b16 {%0,%1,%2,%3}, [%4];"
        : "=r"(r[0]), "=r"(r[1]), "=r"(r[2]), "=r"(r[3]) : "r"(addr));
}

__device__ __forceinline__ uint32_t packh2(float x, float y) {
    __half2 h = __floats2half2_rn(x, y);
    return *(uint32_t*)&h;
}

// ---------------- fp16 weight conversion (single launch) ----------------
__global__ __launch_bounds__(256) void cvtw_all(
    const float* __restrict__ in_w, const float* __restrict__ out_w,
    const float* __restrict__ w1, const float* __restrict__ w2,
    __half* __restrict__ o)
{
    int i = blockIdx.x * 256 + threadIdx.x;
    const float* src;
    int off;
    if (i < 196608)      { src = in_w;  off = i; }
    else if (i < 262144) { src = out_w; off = i - 196608; }
    else if (i < 524288) { src = w1;    off = i - 262144; }
    else                 { src = w2;    off = i - 524288; }
    o[i] = __float2half(src[off]);
}

// ---------------- LayerNorm (LN1): natural -> windowed, half out ----------
__global__ __launch_bounds__(256) void ln_kernel(
    const float* __restrict__ in, const float* __restrict__ g,
    const float* __restrict__ b, __half* __restrict__ out)
{
    int row  = blockIdx.x * 8 + (threadIdx.x >> 5);
    int lane = threadIdx.x & 31;
    int src  = win_to_nat(row);

    const float4* p = (const float4*)(in + (size_t)src * kC);
    float4 v0 = p[lane];
    float4 v1 = p[lane + 32];

    float s  = v0.x + v0.y + v0.z + v0.w + v1.x + v1.y + v1.z + v1.w;
    float s2 = v0.x*v0.x + v0.y*v0.y + v0.z*v0.z + v0.w*v0.w
             + v1.x*v1.x + v1.y*v1.y + v1.z*v1.z + v1.w*v1.w;
    #pragma unroll
    for (int off = 16; off > 0; off >>= 1) {
        s  += __shfl_xor_sync(0xffffffffu, s,  off);
        s2 += __shfl_xor_sync(0xffffffffu, s2, off);
    }
    float mean = s * (1.0f / kC);
    float var  = s2 * (1.0f / kC) - mean * mean;
    float inv  = rsqrtf(var + 1e-5f);

    const float4* gp = (const float4*)g;
    const float4* bp = (const float4*)b;
    float4 g0 = gp[lane], g1 = gp[lane + 32];
    float4 b0 = bp[lane], b1 = bp[lane + 32];

    __half2 h0 = __floats2half2_rn((v0.x - mean) * inv * g0.x + b0.x,
                                   (v0.y - mean) * inv * g0.y + b0.y);
    __half2 h1 = __floats2half2_rn((v0.z - mean) * inv * g0.z + b0.z,
                                   (v0.w - mean) * inv * g0.w + b0.w);
    __half2 h2 = __floats2half2_rn((v1.x - mean) * inv * g1.x + b1.x,
                                   (v1.y - mean) * inv * g1.y + b1.y);
    __half2 h3 = __floats2half2_rn((v1.z - mean) * inv * g1.z + b1.z,
                                   (v1.w - mean) * inv * g1.w + b1.w);

    __half2* q = (__half2*)(out + (size_t)row * kC);
    q[lane * 2]          = h0;
    q[lane * 2 + 1]      = h1;
    q[64 + lane * 2]     = h2;
    q[64 + lane * 2 + 1] = h3;
}

// ---------------- fp16 GEMM: BK=64, 3-stage ring, compile-time K/N --------
constexpr int kGStr   = 72;
constexpr int kGStage = 128 * kGStr;            // 9216 halves per stage/matrix
constexpr int kGemmSmem = 3 * kGStage * 2 * 2;  // 110592 bytes

template <int EPI, int KK, int NN>
__global__ __launch_bounds__(256, 2) void hgemm_kernel(
    const __half* __restrict__ A, const __half* __restrict__ W,
    const float* __restrict__ bias, const float* __restrict__ res,
    void* __restrict__ out_v)
{
    extern __shared__ __half sm[];
    __half* As = sm;
    __half* Bs = sm + 3 * kGStage;

    const int bm   = blockIdx.y * 128;
    const int bn   = blockIdx.x * 128;
    const int tid  = threadIdx.x;
    const int warp = tid >> 5;
    const int lane = tid & 31;
    const int grp  = lane >> 2;
    const int tig  = lane & 3;
    const int wm   = warp & 1;
    const int wn   = warp >> 1;

    const __half* Ag = A + (size_t)bm * KK;
    const __half* Wg = W + (size_t)bn * KK;

    float c[4][4][4];
    #pragma unroll
    for (int i = 0; i < 4; i++)
        #pragma unroll
        for (int j = 0; j < 4; j++)
            #pragma unroll
            for (int r = 0; r < 4; r++) c[i][j][r] = 0.0f;

    constexpr int T = KK >> 6;  // BK = 64

    const int srow = tid >> 3;   // 0..31
    const int sch  = tid & 7;    // 16B chunk within 64-half row

    auto stage_load = [&](int slot, int k0) {
        #pragma unroll
        for (int u = 0; u < 4; u++) {
            int row = srow + u * 32;
            cpa16(&As[slot * kGStage + row * kGStr + sch * 8],
                  Ag + (size_t)row * KK + k0 + sch * 8);
            cpa16(&Bs[slot * kGStage + row * kGStr + sch * 8],
                  Wg + (size_t)row * KK + k0 + sch * 8);
        }
        asm volatile("cp.async.commit_group;");
    };

    stage_load(0, 0);
    stage_load(1, 64);

    const uint32_t smbA = (uint32_t)__cvta_generic_to_shared(As);
    const uint32_t smbB = (uint32_t)__cvta_generic_to_shared(Bs);
    const int aoff = (wm * 64 + (lane & 7) + ((lane >> 3) & 1) * 8) * kGStr
                   + ((lane >> 4) & 1) * 8;
    const int boff0 = (wn * 32 + ((lane >> 4) & 1) * 8 + (lane & 7)) * kGStr
                    + ((lane >> 3) & 1) * 8;
    const int boff1 = boff0 + 16 * kGStr;

    for (int t = 0; t < T; t++) {
        if (t < T - 1) asm volatile("cp.async.wait_group 1;" ::: "memory");
        else           asm volatile("cp.async.wait_group 0;" ::: "memory");
        __syncthreads();

        if (t + 2 < T) stage_load((t + 2) % 3, (t + 2) << 6);

        const int stage = t % 3;
        const uint32_t abase = smbA + (uint32_t)(stage * kGStage) * 2;
        const uint32_t bbase = smbB + (uint32_t)(stage * kGStage) * 2;

        #pragma unroll
        for (int kb = 0; kb < 4; kb++) {
            uint32_t af[4][4];
            uint32_t bq0[4], bq1[4];
            #pragma unroll
            for (int i = 0; i < 4; i++)
                ldsm4(af[i], abase + (uint32_t)(aoff + i * 16 * kGStr + kb * 16) * 2);
            ldsm4(bq0, bbase + (uint32_t)(boff0 + kb * 16) * 2);
            ldsm4(bq1, bbase + (uint32_t)(boff1 + kb * 16) * 2);

            #pragma unroll
            for (int i = 0; i < 4; i++) {
                mma16816(c[i][0], af[i][0], af[i][1], af[i][2], af[i][3], bq0[0], bq0[1]);
                mma16816(c[i][1], af[i][0], af[i][1], af[i][2], af[i][3], bq0[2], bq0[3]);
                mma16816(c[i][2], af[i][0], af[i][1], af[i][2], af[i][3], bq1[0], bq1[1]);
                mma16816(c[i][3], af[i][0], af[i][1], af[i][2], af[i][3], bq1[2], bq1[3]);
            }
        }
    }

    // ---- epilogue ----
    #pragma unroll
    for (int i = 0; i < 4; i++) {
        int mrow0 = bm + wm * 64 + i * 16 + grp;
        int mrow1 = mrow0 + 8;
        #pragma unroll
        for (int j = 0; j < 4; j++) {
            int col = bn + wn * 32 + j * 8 + 2 * tig;
            float2 bv = *(const float2*)&bias[col];
            float v0 = c[i][j][0] + bv.x;
            float v1 = c[i][j][1] + bv.y;
            float v2 = c[i][j][2] + bv.x;
            float v3 = c[i][j][3] + bv.y;
            if (EPI == 0) {
                __half* out = (__half*)out_v;
                *(__half2*)&out[(size_t)mrow0 * NN + col] = __floats2half2_rn(v0, v1);
                *(__half2*)&out[(size_t)mrow1 * NN + col] = __floats2half2_rn(v2, v3);
            } else if (EPI == 1) {
                __half* out = (__half*)out_v;
                *(__half2*)&out[(size_t)mrow0 * NN + col] =
                    __floats2half2_rn(gelu_exact(v0), gelu_exact(v1));
                *(__half2*)&out[(size_t)mrow1 * NN + col] =
                    __floats2half2_rn(gelu_exact(v2), gelu_exact(v3));
            } else {
                float* out = (float*)out_v;
                float2 r0 = *(const float2*)&res[(size_t)mrow0 * 256 + col];
                float2 r1 = *(const float2*)&res[(size_t)mrow1 * 256 + col];
                *(float2*)&out[(size_t)mrow0 * NN + col] = make_float2(v0 + r0.x, v1 + r0.y);
                *(float2*)&out[(size_t)mrow1 * NN + col] = make_float2(v2 + r1.x, v3 + r1.y);
            }
        }
    }
}

// ---- fused out-proj + window-reverse + residual + LN2 (unchanged) ---------
constexpr int kAStr   = 40;
constexpr int kFStageA = 64 * kAStr;    // 2560 halves
constexpr int kFStageB = 256 * kAStr;   // 10240 halves
constexpr int kFusedSmem = 3 * (kFStageA + kFStageB) * 2;  // 76800 bytes

__global__ __launch_bounds__(256, 2) void hgemm_oproj_ln2(
    const __half* __restrict__ A, const __half* __restrict__ W,
    const float* __restrict__ bias, const float* __restrict__ x,
    const float* __restrict__ g2, const float* __restrict__ b2,
    float* __restrict__ x2out, __half* __restrict__ lnout)
{
    extern __shared__ __half sm[];
    __half* As = sm;
    __half* Bs = sm + 3 * kFStageA;
    float*  red = (float*)sm;

    const int K = 256;
    const int bm   = blockIdx.x * 64;
    const int tid  = threadIdx.x;
    const int warp = tid >> 5;
    const int lane = tid & 31;
    const int grp  = lane >> 2;
    const int tig  = lane & 3;

    const __half* Ag = A + (size_t)bm * K;

    float c[4][4][4];
    #pragma unroll
    for (int i = 0; i < 4; i++)
        #pragma unroll
        for (int j = 0; j < 4; j++)
            #pragma unroll
            for (int r = 0; r < 4; r++) c[i][j][r] = 0.0f;

    const int T = K >> 5;  // 8

    const int arow = tid >> 2;
    const int ach  = tid & 3;

    #pragma unroll
    for (int st = 0; st < 2; st++) {
        int k0 = st << 5;
        cpa16(&As[st * kFStageA + arow * kAStr + ach * 8],
              Ag + (size_t)arow * K + k0 + ach * 8);
        #pragma unroll
        for (int u = 0; u < 4; u++) {
            int row = arow + u * 64;
            cpa16(&Bs[st * kFStageB + row * kAStr + ach * 8],
                  W + (size_t)row * K + k0 + ach * 8);
        }
        asm volatile("cp.async.commit_group;");
    }

    const uint32_t smbA = (uint32_t)__cvta_generic_to_shared(As);
    const uint32_t smbB = (uint32_t)__cvta_generic_to_shared(Bs);
    const int aoff = ((lane & 7) + ((lane >> 3) & 1) * 8) * kAStr
                   + ((lane >> 4) & 1) * 8;
    const int boff0 = (warp * 32 + ((lane >> 4) & 1) * 8 + (lane & 7)) * kAStr
                    + ((lane >> 3) & 1) * 8;
    const int boff1 = boff0 + 16 * kAStr;

    for (int t = 0; t < T; t++) {
        if (t < T - 1) asm volatile("cp.async.wait_group 1;" ::: "memory");
        else           asm volatile("cp.async.wait_group 0;" ::: "memory");
        __syncthreads();

        const int stage = t % 3;
        const uint32_t abase = smbA + (uint32_t)(stage * kFStageA) * 2;
        const uint32_t bbase = smbB + (uint32_t)(stage * kFStageB) * 2;

        #pragma unroll
        for (int kb = 0; kb < 2; kb++) {
            uint32_t af[4][4];
            uint32_t bq0[4], bq1[4];
            #pragma unroll
            for (int i = 0; i < 4; i++)
                ldsm4(af[i], abase + (uint32_t)(aoff + i * 16 * kAStr + kb * 16) * 2);
            ldsm4(bq0, bbase + (uint32_t)(boff0 + kb * 16) * 2);
            ldsm4(bq1, bbase + (uint32_t)(boff1 + kb * 16) * 2);

            #pragma unroll
            for (int i = 0; i < 4; i++) {
                mma16816(c[i][0], af[i][0], af[i][1], af[i][2], af[i][3], bq0[0], bq0[1]);
                mma16816(c[i][1], af[i][0], af[i][1], af[i][2], af[i][3], bq0[2], bq0[3]);
                mma16816(c[i][2], af[i][0], af[i][1], af[i][2], af[i][3], bq1[0], bq1[1]);
                mma16816(c[i][3], af[i][0], af[i][1], af[i][2], af[i][3], bq1[2], bq1[3]);
            }
        }

        if (t + 2 < T) {
            int k0 = (t + 2) << 5;
            int st = (t + 2) % 3;
            cpa16(&As[st * kFStageA + arow * kAStr + ach * 8],
                  Ag + (size_t)arow * K + k0 + ach * 8);
            #pragma unroll
            for (int u = 0; u < 4; u++) {
                int row = arow + u * 64;
                cpa16(&Bs[st * kFStageB + row * kAStr + ach * 8],
                      W + (size_t)row * K + k0 + ach * 8);
            }
            asm volatile("cp.async.commit_group;");
        }
    }

    int orow_[8];
    #pragma unroll
    for (int i = 0; i < 4; i++) {
        orow_[i * 2]     = win_to_nat(bm + i * 16 + grp);
        orow_[i * 2 + 1] = win_to_nat(bm + i * 16 + grp + 8);
    }

    float psum[8], psq[8];
    #pragma unroll
    for (int r = 0; r < 8; r++) { psum[r] = 0.0f; psq[r] = 0.0f; }

    #pragma unroll
    for (int i = 0; i < 4; i++) {
        #pragma unroll
        for (int j = 0; j < 4; j++) {
            int col = warp * 32 + j * 8 + 2 * tig;
            float2 bv = *(const float2*)&bias[col];
            float2 r0 = *(const float2*)&x[(size_t)orow_[i*2]   * 256 + col];
            float2 r1 = *(const float2*)&x[(size_t)orow_[i*2+1] * 256 + col];
            c[i][j][0] += bv.x + r0.x;
            c[i][j][1] += bv.y + r0.y;
            c[i][j][2] += bv.x + r1.x;
            c[i][j][3] += bv.y + r1.y;
            *(float2*)&x2out[(size_t)orow_[i*2]   * 256 + col] = make_float2(c[i][j][0], c[i][j][1]);
            *(float2*)&x2out[(size_t)orow_[i*2+1] * 256 + col] = make_float2(c[i][j][2], c[i][j][3]);
            psum[i*2]   += c[i][j][0] + c[i][j][1];
            psq[i*2]    += c[i][j][0]*c[i][j][0] + c[i][j][1]*c[i][j][1];
            psum[i*2+1] += c[i][j][2] + c[i][j][3];
            psq[i*2+1]  += c[i][j][2]*c[i][j][2] + c[i][j][3]*c[i][j][3];
        }
    }

    #pragma unroll
    for (int r = 0; r < 8; r++) {
        psum[r] += __shfl_xor_sync(0xffffffffu, psum[r], 1);
        psum[r] += __shfl_xor_sync(0xffffffffu, psum[r], 2);
        psq[r]  += __shfl_xor_sync(0xffffffffu, psq[r], 1);
        psq[r]  += __shfl_xor_sync(0xffffffffu, psq[r], 2);
    }

    __syncthreads();
    if (tig == 0) {
        #pragma unroll
        for (int i = 0; i < 4; i++) {
            int r0 = i * 16 + grp, r1 = r0 + 8;
            red[(r0 * 8 + warp) * 2]     = psum[i*2];
            red[(r0 * 8 + warp) * 2 + 1] = psq[i*2];
            red[(r1 * 8 + warp) * 2]     = psum[i*2+1];
            red[(r1 * 8 + warp) * 2 + 1] = psq[i*2+1];
        }
    }
    __syncthreads();

    if (tid < 64) {
        float s = 0.0f, sq = 0.0f;
        #pragma unroll
        for (int wdx = 0; wdx < 8; wdx++) {
            s  += red[(tid * 8 + wdx) * 2];
            sq += red[(tid * 8 + wdx) * 2 + 1];
        }
        float mean = s * (1.0f / 256.0f);
        float var  = sq * (1.0f / 256.0f) - mean * mean;
        red[1024 + tid * 2]     = mean;
        red[1024 + tid * 2 + 1] = rsqrtf(var + 1e-5f);
    }
    __syncthreads();

    #pragma unroll
    for (int i = 0; i < 4; i++) {
        int r0 = i * 16 + grp, r1 = r0 + 8;
        float m0 = red[1024 + r0 * 2], v0i = red[1024 + r0 * 2 + 1];
        float m1 = red[1024 + r1 * 2], v1i = red[1024 + r1 * 2 + 1];
        #pragma unroll
        for (int j = 0; j < 4; j++) {
            int col = warp * 32 + j * 8 + 2 * tig;
            float2 gg = *(const float2*)&g2[col];
            float2 bb = *(const float2*)&b2[col];
            *(__half2*)&lnout[(size_t)orow_[i*2] * 256 + col] =
                __floats2half2_rn((c[i][j][0] - m0) * v0i * gg.x + bb.x,
                                  (c[i][j][1] - m0) * v0i * gg.y + bb.y);
            *(__half2*)&lnout[(size_t)orow_[i*2+1] * 256 + col] =
                __floats2half2_rn((c[i][j][2] - m1) * v1i * gg.x + bb.x,
                                  (c[i][j][3] - m1) * v1i * gg.y + bb.y);
        }
    }
}

// ---------------- mma window attention: cp.async staging -------------------
constexpr int kQKstr = 264;
constexpr int kVstr  = 264;
constexpr int kQoff  = 0;
constexpr int kKoff  = 64 * kQKstr;
constexpr int kVoff  = 2 * 64 * kQKstr;
constexpr int kAttnSmem = (kVoff + 64 * kVstr) * 2;   // 101376 B

__global__ __launch_bounds__(256, 2) void attn_mma_kernel(
    const __half* __restrict__ qkv, __half* __restrict__ o)
{
    extern __shared__ __half sm[];
    const int tid  = threadIdx.x;
    const int win  = blockIdx.x;
    const int h    = tid >> 5;
    const int lane = tid & 31;
    const int grp  = lane >> 2;
    const int tig  = lane & 3;

    // ---- stage Q, K, V via cp.async (deep MLP, no register round-trip) ----
    const __half* gbase = qkv + (size_t)win * 64 * 768;
    #pragma unroll
    for (int u = 0; u < 8; u++) {
        int idx = tid + u * 256;
        int t   = idx >> 5;
        int c8  = (idx & 31) << 3;
        const __half* gp = gbase + t * 768 + c8;
        cpa16(&sm[kQoff + t * kQKstr + c8], gp);
        cpa16(&sm[kKoff + t * kQKstr + c8], gp + 256);
        cpa16(&sm[kVoff + t * kVstr  + c8], gp + 512);
    }
    asm volatile("cp.async.commit_group;");
    asm volatile("cp.async.wait_group 0;" ::: "memory");
    __syncthreads();

    const uint32_t smb = (uint32_t)__cvta_generic_to_shared(sm);

    // ---- V fragments (resident, ldmatrix.trans) ----
    uint32_t bf[4][4][2];
    {
        int srow = (lane & 7) + ((lane >> 3) & 1) * 8;
        int dcol = h * 32 + (lane >> 4) * 8;
        #pragma unroll
        for (int kk = 0; kk < 4; kk++) {
            #pragma unroll
            for (int jp = 0; jp < 2; jp++) {
                uint32_t addr = smb +
                    (uint32_t)(kVoff + (kk * 16 + srow) * kVstr + dcol + jp * 16) * 2;
                uint32_t r[4];
                ldsm4t(r, addr);
                bf[kk][jp * 2 + 0][0] = r[0];
                bf[kk][jp * 2 + 0][1] = r[1];
                bf[kk][jp * 2 + 1][0] = r[2];
                bf[kk][jp * 2 + 1][1] = r[3];
            }
        }
    }

    const int qrow = (lane & 7) + ((lane >> 3) & 1) * 8;
    const int qcol = h * 32 + ((lane >> 4) & 1) * 8;
    const int krow = ((lane >> 4) & 1) * 8 + (lane & 7);
    const int kcolb = h * 32 + ((lane >> 3) & 1) * 8;

    const float scale = 0.17677669529663687f;

    #pragma unroll
    for (int i = 0; i < 4; i++) {
        float s[8][4];
        #pragma unroll
        for (int j = 0; j < 8; j++)
            #pragma unroll
            for (int r = 0; r < 4; r++) s[j][r] = 0.0f;

        #pragma unroll
        for (int kb = 0; kb < 2; kb++) {
            uint32_t qf[4];
            ldsm4(qf, smb + (uint32_t)(kQoff + (i * 16 + qrow) * kQKstr
                                       + qcol + kb * 16) * 2);
            #pragma unroll
            for (int jj = 0; jj < 4; jj++) {
                uint32_t kq[4];
                ldsm4(kq, smb + (uint32_t)(kKoff + (jj * 16 + krow) * kQKstr
                                           + kcolb + kb * 16) * 2);
                mma16816(s[2 * jj],     qf[0], qf[1], qf[2], qf[3], kq[0], kq[1]);
                mma16816(s[2 * jj + 1], qf[0], qf[1], qf[2], qf[3], kq[2], kq[3]);
            }
        }

        float mx0 = -1e30f, mx1 = -1e30f;
        #pragma unroll
        for (int j = 0; j < 8; j++) {
            mx0 = fmaxf(mx0, fmaxf(s[j][0], s[j][1]));
            mx1 = fmaxf(mx1, fmaxf(s[j][2], s[j][3]));
        }
        mx0 = fmaxf(mx0, __shfl_xor_sync(0xffffffffu, mx0, 1));
        mx0 = fmaxf(mx0, __shfl_xor_sync(0xffffffffu, mx0, 2));
        mx1 = fmaxf(mx1, __shfl_xor_sync(0xffffffffu, mx1, 1));
        mx1 = fmaxf(mx1, __shfl_xor_sync(0xffffffffu, mx1, 2));

        float sum0 = 0.0f, sum1 = 0.0f;
        #pragma unroll
        for (int j = 0; j < 8; j++) {
            s[j][0] = __expf((s[j][0] - mx0) * scale);
            s[j][1] = __expf((s[j][1] - mx0) * scale);
            s[j][2] = __expf((s[j][2] - mx1) * scale);
            s[j][3] = __expf((s[j][3] - mx1) * scale);
            sum0 += s[j][0] + s[j][1];
            sum1 += s[j][2] + s[j][3];
        }
        sum0 += __shfl_xor_sync(0xffffffffu, sum0, 1);
        sum0 += __shfl_xor_sync(0xffffffffu, sum0, 2);
        sum1 += __shfl_xor_sync(0xffffffffu, sum1, 1);
        sum1 += __shfl_xor_sync(0xffffffffu, sum1, 2);
        float inv0 = 1.0f / sum0;
        float inv1 = 1.0f / sum1;

        uint32_t ph0[8], ph1[8];
        #pragma unroll
        for (int j = 0; j < 8; j++) {
            ph0[j] = packh2(s[j][0] * inv0, s[j][1] * inv0);
            ph1[j] = packh2(s[j][2] * inv1, s[j][3] * inv1);
        }

        float oa[4][4];
        #pragma unroll
        for (int jn = 0; jn < 4; jn++)
            #pragma unroll
            for (int r = 0; r < 4; r++) oa[jn][r] = 0.0f;

        #pragma unroll
        for (int kk = 0; kk < 4; kk++)
            #pragma unroll
            for (int jn = 0; jn < 4; jn++)
                mma16816(oa[jn], ph0[2 * kk], ph1[2 * kk],
                         ph0[2 * kk + 1], ph1[2 * kk + 1],
                         bf[kk][jn][0], bf[kk][jn][1]);

        int gr = win * 64 + i * 16 + grp;
        #pragma unroll
        for (int jn = 0; jn < 4; jn++) {
            int col = h * 32 + jn * 8 + tig * 2;
            *(__half2*)&o[(size_t)gr * 256 + col] =
                __floats2half2_rn(oa[jn][0], oa[jn][1]);
            *(__half2*)&o[(size_t)(gr + 8) * 256 + col] =
                __floats2half2_rn(oa[jn][2], oa[jn][3]);
        }
    }
}

// ---------------- launch ----------------
extern "C" void kernel_launch(void* const* d_in, const int* in_sizes, int n_in,
                              void* d_out, int out_size)
{
    const float* x     = (const float*)d_in[0];
    const float* ln1_g = (const float*)d_in[1];
    const float* ln1_b = (const float*)d_in[2];
    const float* in_w  = (const float*)d_in[3];
    const float* in_b  = (const float*)d_in[4];
    const float* out_w = (const float*)d_in[5];
    const float* out_b = (const float*)d_in[6];
    const float* ln2_g = (const float*)d_in[7];
    const float* ln2_b = (const float*)d_in[8];
    const float* w1    = (const float*)d_in[9];
    const float* b1    = (const float*)d_in[10];
    const float* w2    = (const float*)d_in[11];
    const float* b2    = (const float*)d_in[12];
    float* out = (float*)d_out;

    __half *big, *a, *bb, *w;
    float *cc;
    cudaGetSymbolAddress((void**)&big, g_big);
    cudaGetSymbolAddress((void**)&a,   g_a);
    cudaGetSymbolAddress((void**)&bb,  g_b);
    cudaGetSymbolAddress((void**)&cc,  g_c);
    cudaGetSymbolAddress((void**)&w,   g_w);

    __half* w_in  = w;
    __half* w_out = w + 196608;
    __half* w_1   = w + 262144;
    __half* w_2   = w + 524288;

    cudaFuncSetAttribute(attn_mma_kernel,
                         cudaFuncAttributeMaxDynamicSharedMemorySize, kAttnSmem);
    cudaFuncSetAttribute((hgemm_kernel<0, 256, 768>),
                         cudaFuncAttributeMaxDynamicSharedMemorySize, kGemmSmem);
    cudaFuncSetAttribute((hgemm_kernel<1, 256, 1024>),
                         cudaFuncAttributeMaxDynamicSharedMemorySize, kGemmSmem);
    cudaFuncSetAttribute((hgemm_kernel<3, 1024, 256>),
                         cudaFuncAttributeMaxDynamicSharedMemorySize, kGemmSmem);
    cudaFuncSetAttribute(hgemm_oproj_ln2,
                         cudaFuncAttributeMaxDynamicSharedMemorySize, kFusedSmem);

    // 0) fp16 weights (single launch)
    cvtw_all<<<3072, 256>>>(in_w, out_w, w1, w2, w);
    // 1) LN1, natural -> windowed order, half out
    ln_kernel<<<kM / 8, 256>>>(x, ln1_g, ln1_b, a);
    // 2) QKV projection
    hgemm_kernel<0, 256, 768><<<dim3(6, kM / 128), 256, kGemmSmem>>>(a, w_in, in_b, nullptr, big);
    // 3) windowed attention (tensor-core, cp.async staging)
    attn_mma_kernel<<<kNWin, 256, kAttnSmem>>>(big, bb);
    // 4) out-proj + window-reverse + residual + LN2 (fused)
    hgemm_oproj_ln2<<<kM / 64, 256, kFusedSmem>>>(bb, w_out, out_b, x, ln2_g, ln2_b, cc, a);
    // 5) MLP up + exact GELU
    hgemm_kernel<1, 256, 1024><<<dim3(8, kM / 128), 256, kGemmSmem>>>(a, w_1, b1, nullptr, big);
    // 6) MLP down + residual -> fp32 final output
    hgemm_kernel<3, 1024, 256><<<dim3(2, kM / 128), 256, kGemmSmem>>>(big, w_2, b2, cc, out);
}